// round 2
// baseline (speedup 1.0000x reference)
#include <cuda_runtime.h>
#include <math.h>
#include <stdint.h>

// ---------------------------------------------------------------------------
// ExpressionBert forward, fp32, correctness-first round.
// All dense GEMMs via a textbook-verifiable tiled kernel (tgemm).
// Attention scores computed directly (q.k + (q+k).dist[l-r+255]) with smem
// staging; no QD/KD reformulation.
// ---------------------------------------------------------------------------

#define LNUM   4
#define DIM    512
#define NHEAD  4
#define DHD    128
#define FFI    128
#define SEQ    256
#define BATCH  128
#define NFEAT  6
#define TOK    (BATCH*SEQ)          // 32768
#define PP     511
#define ROWSBH (BATCH*NHEAD*SEQ)    // 131072

#define SM_SCALE 0.08838834764831845f  // 1/sqrt(128)

// ------------------------- static device scratch ---------------------------
__device__ float g_X  [TOK*DIM];
__device__ float g_Q  [TOK*DIM];
__device__ float g_K  [TOK*DIM];
__device__ float g_V  [TOK*DIM];
__device__ float g_CTX[TOK*DIM];
__device__ float g_TMP[TOK*DIM];
__device__ float g_SC [(size_t)BATCH*NHEAD*SEQ*SEQ];
__device__ float g_Hb [TOK*FFI];

// ------------------------------ helpers ------------------------------------
__device__ __forceinline__ float gelu_exact(float x) {
    return 0.5f * x * (1.0f + erff(x * 0.70710678118654752440f));
}

__device__ __forceinline__ void block_reduce2(float& a, float& b) {
    __shared__ float sa[8], sb[8];
    int lane = threadIdx.x & 31, w = threadIdx.x >> 5;
    #pragma unroll
    for (int o = 16; o; o >>= 1) {
        a += __shfl_xor_sync(0xffffffffu, a, o);
        b += __shfl_xor_sync(0xffffffffu, b, o);
    }
    if (lane == 0) { sa[w] = a; sb[w] = b; }
    __syncthreads();
    if (w == 0) {
        a = (lane < 8) ? sa[lane] : 0.0f;
        b = (lane < 8) ? sb[lane] : 0.0f;
        #pragma unroll
        for (int o = 4; o; o >>= 1) {
            a += __shfl_xor_sync(0xffffffffu, a, o);
            b += __shfl_xor_sync(0xffffffffu, b, o);
        }
        if (lane == 0) { sa[0] = a; sb[0] = b; }
    }
    __syncthreads();
    a = sa[0]; b = sb[0];
}

// --------------------------- embedding + LN --------------------------------
__global__ void embed_ln(const int* __restrict__ ids, const float* __restrict__ inW,
                         const float* __restrict__ inb, const float* __restrict__ tok,
                         const float* __restrict__ g,  const float* __restrict__ bb,
                         float* __restrict__ X) {
    int t = blockIdx.x, tid = threadIdx.x;
    float f[NFEAT];
    #pragma unroll
    for (int i = 0; i < NFEAT; i++) f[i] = (float)ids[t * NFEAT + i];
    int d0 = tid, d1 = tid + 256;
    float v0 = inb[d0] + tok[d0];
    float v1 = inb[d1] + tok[d1];
    #pragma unroll
    for (int i = 0; i < NFEAT; i++) {
        v0 += f[i] * inW[i * DIM + d0];
        v1 += f[i] * inW[i * DIM + d1];
    }
    float s = v0 + v1, q = v0 * v0 + v1 * v1;
    block_reduce2(s, q);
    float mu  = s * (1.0f / DIM);
    float var = q * (1.0f / DIM) - mu * mu;
    float r   = rsqrtf(var + 1e-12f);
    X[(size_t)t * DIM + d0] = (v0 - mu) * r * g[d0] + bb[d0];
    X[(size_t)t * DIM + d1] = (v1 - mu) * r * g[d1] + bb[d1];
}

__global__ void ln_res(const float* __restrict__ X, const float* __restrict__ Y,
                       const float* __restrict__ g, const float* __restrict__ bb,
                       float* __restrict__ out) {
    int t = blockIdx.x, tid = threadIdx.x;
    int d0 = tid, d1 = tid + 256;
    size_t base = (size_t)t * DIM;
    float v0 = X[base + d0] + Y[base + d0];
    float v1 = X[base + d1] + Y[base + d1];
    float s = v0 + v1, q = v0 * v0 + v1 * v1;
    block_reduce2(s, q);
    float mu  = s * (1.0f / DIM);
    float var = q * (1.0f / DIM) - mu * mu;
    float r   = rsqrtf(var + 1e-12f);
    out[base + d0] = (v0 - mu) * r * g[d0] + bb[d0];
    out[base + d1] = (v1 - mu) * r * g[d1] + bb[d1];
}

// ------------------------------ simple GEMM ---------------------------------
// C[M,N] = A[M,K] @ B[K,N] + bias (+GELU). Tile: 128 rows x 16 cols, block
// (16,16), 8 rows per thread. M must be a multiple of 128, K of 16.
template<int ACT>
__global__ void tgemm(const float* __restrict__ A, int lda,
                      const float* __restrict__ B, int ldb,
                      const float* __restrict__ bias,
                      float* __restrict__ C, int ldc,
                      int M, int N, int K) {
    __shared__ float As[128][17];
    __shared__ float Bs[16][17];
    int tx = threadIdx.x, ty = threadIdx.y;      // 16 x 16
    int m0 = blockIdx.y * 128;
    int n  = blockIdx.x * 16 + tx;
    float acc[8] = {};
    for (int k0 = 0; k0 < K; k0 += 16) {
        #pragma unroll
        for (int i = 0; i < 8; i++) {
            int mr = ty + i * 16;
            As[mr][tx] = A[(size_t)(m0 + mr) * lda + k0 + tx];
        }
        Bs[ty][tx] = (n < N) ? B[(size_t)(k0 + ty) * ldb + n] : 0.0f;
        __syncthreads();
        #pragma unroll
        for (int kk = 0; kk < 16; kk++) {
            float b = Bs[kk][tx];
            #pragma unroll
            for (int i = 0; i < 8; i++)
                acc[i] += As[ty + i * 16][kk] * b;
        }
        __syncthreads();
    }
    if (n < N) {
        float bv = bias ? bias[n] : 0.0f;
        #pragma unroll
        for (int i = 0; i < 8; i++) {
            float v = acc[i] + bv;
            if (ACT == 1) v = gelu_exact(v);
            C[(size_t)(m0 + ty + i * 16) * ldc + n] = v;
        }
    }
}

// ----------------------- attention scores (direct pe) ----------------------
// grid (S/16, S/16, B*H), block (16,16).
// score[l,r] = q[l].k[r] + (q[l]+k[r]).dist[l-r+255]
__global__ void attn_scores_simple(const float* __restrict__ Q,
                                   const float* __restrict__ Km,
                                   const float* __restrict__ dist,
                                   float* __restrict__ SC) {
    __shared__ float qs[16][129];
    __shared__ float ks[16][129];
    __shared__ float ds[31][129];
    int tx = threadIdx.x, ty = threadIdx.y;
    int tid = ty * 16 + tx;
    int bh = blockIdx.z;
    int b = bh >> 2, h = bh & 3;
    int l0 = blockIdx.y * 16;
    int r0 = blockIdx.x * 16;
    const float* qb = Q  + (size_t)b * SEQ * DIM + h * DHD;
    const float* kb = Km + (size_t)b * SEQ * DIM + h * DHD;
    // stage q,k tiles (16 x 128 each)
    #pragma unroll
    for (int j = 0; j < 8; j++) {
        int idx = tid + j * 256;
        int row = idx >> 7, col = idx & 127;
        qs[row][col] = qb[(size_t)(l0 + row) * DIM + col];
        ks[row][col] = kb[(size_t)(r0 + row) * DIM + col];
    }
    // stage the 31 dist rows this tile needs: p in [pmin, pmin+30]
    int pmin = l0 - r0 + 240;
    for (int idx = tid; idx < 31 * 128; idx += 256) {
        int row = idx >> 7, col = idx & 127;
        ds[row][col] = dist[(size_t)(pmin + row) * DHD + col];
    }
    __syncthreads();
    int prow = ty - tx + 15;   // (l-r+255) - pmin
    float s = 0.0f;
    #pragma unroll 8
    for (int d = 0; d < DHD; d++) {
        float qv = qs[ty][d], kv = ks[tx][d], dv = ds[prow][d];
        s += qv * kv + (qv + kv) * dv;
    }
    int l = l0 + ty, r = r0 + tx;
    SC[((size_t)bh * SEQ + l) * SEQ + r] = s;
}

// ------------------------------- softmax ------------------------------------
__global__ void softmax_rows(float* __restrict__ SC, const float* __restrict__ mask) {
    int row  = blockIdx.x * 8 + (threadIdx.x >> 5);
    int lane = threadIdx.x & 31;
    int b = row / (NHEAD * SEQ);
    float* p = SC + (size_t)row * SEQ;
    const float* m = mask + (size_t)b * SEQ;
    float v[8];
    float mx = -1e30f;
    #pragma unroll
    for (int i = 0; i < 8; i++) {
        int r = lane + i * 32;
        float s = p[r] * SM_SCALE + (1.0f - m[r]) * (-1e9f);
        v[i] = s;
        mx = fmaxf(mx, s);
    }
    #pragma unroll
    for (int o = 16; o; o >>= 1) mx = fmaxf(mx, __shfl_xor_sync(0xffffffffu, mx, o));
    float sum = 0.0f;
    #pragma unroll
    for (int i = 0; i < 8; i++) { v[i] = __expf(v[i] - mx); sum += v[i]; }
    #pragma unroll
    for (int o = 16; o; o >>= 1) sum += __shfl_xor_sync(0xffffffffu, sum, o);
    float inv = 1.0f / sum;
    #pragma unroll
    for (int i = 0; i < 8; i++) p[lane + i * 32] = v[i] * inv;
}

// ------------------------------ ctx = P @ V ---------------------------------
// grid (DHD/16, S/16, B*H), block (16,16). Textbook tiling.
__global__ void attn_ctx_simple(const float* __restrict__ P,
                                const float* __restrict__ V,
                                float* __restrict__ CTX) {
    __shared__ float Ps[16][17];
    __shared__ float Vs[16][17];
    int tx = threadIdx.x, ty = threadIdx.y;
    int bh = blockIdx.z;
    int b = bh >> 2, h = bh & 3;
    int l0 = blockIdx.y * 16;
    int n0 = blockIdx.x * 16;
    const float* Pp = P + (size_t)bh * SEQ * SEQ;
    const float* Vb = V + (size_t)b * SEQ * DIM + h * DHD;
    float acc = 0.0f;
    for (int k0 = 0; k0 < SEQ; k0 += 16) {
        Ps[ty][tx] = Pp[(size_t)(l0 + ty) * SEQ + k0 + tx];
        Vs[ty][tx] = Vb[(size_t)(k0 + ty) * DIM + n0 + tx];
        __syncthreads();
        #pragma unroll
        for (int kk = 0; kk < 16; kk++)
            acc += Ps[ty][kk] * Vs[kk][tx];
        __syncthreads();
    }
    CTX[(size_t)b * SEQ * DIM + (size_t)(l0 + ty) * DIM + h * DHD + n0 + tx] = acc;
}

// ------------------------------ host driver --------------------------------
extern "C" void kernel_launch(void* const* d_in, const int* in_sizes, int n_in,
                              void* d_out, int out_size) {
    (void)in_sizes; (void)n_in; (void)out_size;
    const int*   ids  = (const int*)  d_in[0];
    const float* mask = (const float*)d_in[1];
    const float* inW  = (const float*)d_in[2];
    const float* inb  = (const float*)d_in[3];
    const float* tok  = (const float*)d_in[4];
    const float* elg  = (const float*)d_in[5];
    const float* elb  = (const float*)d_in[6];
    const float* dist = (const float*)d_in[7];
    const float* Wq   = (const float*)d_in[8];
    const float* bq   = (const float*)d_in[9];
    const float* Wk   = (const float*)d_in[10];
    const float* bk   = (const float*)d_in[11];
    const float* Wv   = (const float*)d_in[12];
    const float* bv   = (const float*)d_in[13];
    const float* Wo   = (const float*)d_in[14];
    const float* bo   = (const float*)d_in[15];
    const float* ln1g = (const float*)d_in[16];
    const float* ln1b = (const float*)d_in[17];
    const float* Wi   = (const float*)d_in[18];
    const float* bi   = (const float*)d_in[19];
    const float* Wo2  = (const float*)d_in[20];
    const float* bo2  = (const float*)d_in[21];
    const float* ln2g = (const float*)d_in[22];
    const float* ln2b = (const float*)d_in[23];
    float* out = (float*)d_out;

    float *X, *Q, *Kb, *V, *CTX, *TMP, *SC, *Hb;
    cudaGetSymbolAddress((void**)&X,   g_X);
    cudaGetSymbolAddress((void**)&Q,   g_Q);
    cudaGetSymbolAddress((void**)&Kb,  g_K);
    cudaGetSymbolAddress((void**)&V,   g_V);
    cudaGetSymbolAddress((void**)&CTX, g_CTX);
    cudaGetSymbolAddress((void**)&TMP, g_TMP);
    cudaGetSymbolAddress((void**)&SC,  g_SC);
    cudaGetSymbolAddress((void**)&Hb,  g_Hb);

    embed_ln<<<TOK, 256>>>(ids, inW, inb, tok, elg, elb, X);

    dim3 blk(16, 16);
    dim3 gX(DIM / 16, TOK / 128);               // 32 x 256
    dim3 gF(FFI / 16, TOK / 128);               // 8 x 256
    dim3 gS(SEQ / 16, SEQ / 16, BATCH * NHEAD); // 16 x 16 x 512
    dim3 gC(DHD / 16, SEQ / 16, BATCH * NHEAD); // 8 x 16 x 512

    for (int l = 0; l < LNUM; l++) {
        const float* wq  = Wq  + (size_t)l * DIM * DIM;
        const float* wk  = Wk  + (size_t)l * DIM * DIM;
        const float* wv  = Wv  + (size_t)l * DIM * DIM;
        const float* wo  = Wo  + (size_t)l * DIM * DIM;
        const float* wi  = Wi  + (size_t)l * DIM * FFI;
        const float* wo2 = Wo2 + (size_t)l * FFI * DIM;

        tgemm<0><<<gX, blk>>>(X, DIM, wq, DIM, bq + l * DIM, Q,  DIM, TOK, DIM, DIM);
        tgemm<0><<<gX, blk>>>(X, DIM, wk, DIM, bk + l * DIM, Kb, DIM, TOK, DIM, DIM);
        tgemm<0><<<gX, blk>>>(X, DIM, wv, DIM, bv + l * DIM, V,  DIM, TOK, DIM, DIM);

        attn_scores_simple<<<gS, blk>>>(Q, Kb, dist, SC);
        softmax_rows<<<ROWSBH / 8, 256>>>(SC, mask);
        attn_ctx_simple<<<gC, blk>>>(SC, V, CTX);

        tgemm<0><<<gX, blk>>>(CTX, DIM, wo, DIM, bo + l * DIM, TMP, DIM, TOK, DIM, DIM);
        ln_res<<<TOK, 256>>>(X, TMP, ln1g + l * DIM, ln1b + l * DIM, X);

        tgemm<1><<<gF, blk>>>(X, DIM, wi, FFI, bi + l * FFI, Hb, FFI, TOK, FFI, DIM);
        tgemm<0><<<gX, blk>>>(Hb, FFI, wo2, DIM, bo2 + l * DIM, TMP, DIM, TOK, DIM, FFI);
        ln_res<<<TOK, 256>>>(X, TMP, ln2g + l * DIM, ln2b + l * DIM,
                             (l == LNUM - 1) ? out : X);
    }
}

// round 5
// speedup vs baseline: 2.4263x; 2.4263x over previous
#include <cuda_runtime.h>
#include <math.h>
#include <stdint.h>

// ---------------------------------------------------------------------------
// ExpressionBert forward. Dense GEMMs on portable tensor-core path using
// tf32 mma.sync (m16n8k8, fp32 accum) — bf16 inputs failed rel_err by 8%;
// tf32's 11 mantissa bits give ~8x better input rounding. All buffers fp32.
// Attention scores/softmax/ctx + LayerNorms in fp32 (round-2 verified).
// ---------------------------------------------------------------------------

#define LNUM   4
#define DIM    512
#define NHEAD  4
#define DHD    128
#define FFI    128
#define SEQ    256
#define BATCH  128
#define NFEAT  6
#define TOK    (BATCH*SEQ)          // 32768
#define ROWSBH (BATCH*NHEAD*SEQ)    // 131072

#define SM_SCALE 0.08838834764831845f  // 1/sqrt(128)

// ------------------------- static device scratch ---------------------------
__device__ float g_X  [TOK*DIM];
__device__ float g_Q  [TOK*DIM];
__device__ float g_K  [TOK*DIM];
__device__ float g_V  [TOK*DIM];
__device__ float g_CTX[TOK*DIM];
__device__ float g_TMP[TOK*DIM];
__device__ float g_Hb [TOK*FFI];
__device__ float g_SC [(size_t)BATCH*NHEAD*SEQ*SEQ];

__device__ float g_WqT [LNUM*DIM*DIM];
__device__ float g_WkT [LNUM*DIM*DIM];
__device__ float g_WvT [LNUM*DIM*DIM];
__device__ float g_WoT [LNUM*DIM*DIM];
__device__ float g_WiT [LNUM*FFI*DIM];   // [I rows][D cols]
__device__ float g_Wo2T[LNUM*DIM*FFI];   // [D rows][I cols]

// ------------------------------ helpers -------------------------------------
__device__ __forceinline__ float gelu_exact(float x) {
    return 0.5f * x * (1.0f + erff(x * 0.70710678118654752440f));
}

__device__ __forceinline__ uint32_t f2tf32(float f) {
    uint32_t u;
    asm("cvt.rna.tf32.f32 %0, %1;" : "=r"(u) : "f"(f));
    return u;
}

__device__ __forceinline__ void mma_tf32(float* d, const uint32_t* a,
                                         const uint32_t* b) {
    asm volatile(
        "mma.sync.aligned.m16n8k8.row.col.f32.tf32.tf32.f32 "
        "{%0,%1,%2,%3}, {%4,%5,%6,%7}, {%8,%9}, {%0,%1,%2,%3};"
        : "+f"(d[0]), "+f"(d[1]), "+f"(d[2]), "+f"(d[3])
        : "r"(a[0]), "r"(a[1]), "r"(a[2]), "r"(a[3]), "r"(b[0]), "r"(b[1]));
}

// ----------------------- tensor-core tf32 GEMM ------------------------------
// C[M,N] = A[M,K] @ BT[N,K]^T + bias (+GELU). fp32 in/out, tf32 compute.
// Block tile 128x128, 256 threads = 8 warps (4 M x 2 N), warp tile 32x64.
// K staged in 32-wide chunks; smem row stride 36 floats -> LDS fragment
// reads hit bank (4g+t)%32, a perfect warp permutation (conflict-free).
#define SST 36

template<int GELU>
__global__ __launch_bounds__(256) void gemm_tf32(
    const float* __restrict__ A,    // [M][K] row-major
    const float* __restrict__ BT,   // [N][K] row-major
    const float* __restrict__ bias, // [N] or null
    float* __restrict__ C,
    int K, int N) {
    __shared__ __align__(16) uint32_t sA[128 * SST];
    __shared__ __align__(16) uint32_t sB[128 * SST];

    int tid  = threadIdx.x;
    int wid  = tid >> 5, lane = tid & 31;
    int g    = lane >> 2, t = lane & 3;
    int m0   = blockIdx.y * 128;
    int n0   = blockIdx.x * 128;
    int wm   = wid >> 1, wn = wid & 1;
    int mbase = wm * 32, nbase = wn * 64;

    float acc[2][8][4];
    #pragma unroll
    for (int i = 0; i < 2; i++)
        #pragma unroll
        for (int j = 0; j < 8; j++)
            #pragma unroll
            for (int q = 0; q < 4; q++) acc[i][j][q] = 0.0f;

    int nch = K >> 5;
    for (int c = 0; c < nch; c++) {
        // stage 128x32 fp32 chunks of A and BT, converting to tf32
        #pragma unroll
        for (int i = 0; i < 4; i++) {
            int idx = tid + i * 256;          // 0..1023
            int row = idx >> 3;               // 0..127
            int seg = idx & 7;                // 4 floats each
            float4 va = *reinterpret_cast<const float4*>(
                &A[(size_t)(m0 + row) * K + c * 32 + seg * 4]);
            uint32_t* pa = &sA[row * SST + seg * 4];
            pa[0] = f2tf32(va.x); pa[1] = f2tf32(va.y);
            pa[2] = f2tf32(va.z); pa[3] = f2tf32(va.w);
            float4 vb = *reinterpret_cast<const float4*>(
                &BT[(size_t)(n0 + row) * K + c * 32 + seg * 4]);
            uint32_t* pb = &sB[row * SST + seg * 4];
            pb[0] = f2tf32(vb.x); pb[1] = f2tf32(vb.y);
            pb[2] = f2tf32(vb.z); pb[3] = f2tf32(vb.w);
        }
        __syncthreads();

        #pragma unroll
        for (int kk = 0; kk < 32; kk += 8) {
            uint32_t af[2][4];
            #pragma unroll
            for (int mt = 0; mt < 2; mt++) {
                int r = mbase + mt * 16 + g;
                af[mt][0] = sA[r * SST + kk + t];
                af[mt][1] = sA[(r + 8) * SST + kk + t];
                af[mt][2] = sA[r * SST + kk + t + 4];
                af[mt][3] = sA[(r + 8) * SST + kk + t + 4];
            }
            uint32_t bf[8][2];
            #pragma unroll
            for (int nt = 0; nt < 8; nt++) {
                int r = nbase + nt * 8 + g;
                bf[nt][0] = sB[r * SST + kk + t];
                bf[nt][1] = sB[r * SST + kk + t + 4];
            }
            #pragma unroll
            for (int mt = 0; mt < 2; mt++)
                #pragma unroll
                for (int nt = 0; nt < 8; nt++)
                    mma_tf32(acc[mt][nt], af[mt], bf[nt]);
        }
        __syncthreads();
    }

    // epilogue: c0,c1 -> (row g, cols 2t,2t+1); c2,c3 -> row g+8
    #pragma unroll
    for (int mt = 0; mt < 2; mt++) {
        #pragma unroll
        for (int nt = 0; nt < 8; nt++) {
            int col = n0 + nbase + nt * 8 + 2 * t;
            float b0 = bias ? bias[col]     : 0.0f;
            float b1 = bias ? bias[col + 1] : 0.0f;
            int r0 = m0 + mbase + mt * 16 + g;
            int r1 = r0 + 8;
            float v00 = acc[mt][nt][0] + b0, v01 = acc[mt][nt][1] + b1;
            float v10 = acc[mt][nt][2] + b0, v11 = acc[mt][nt][3] + b1;
            if (GELU) {
                v00 = gelu_exact(v00); v01 = gelu_exact(v01);
                v10 = gelu_exact(v10); v11 = gelu_exact(v11);
            }
            *reinterpret_cast<float2*>(&C[(size_t)r0 * N + col]) = make_float2(v00, v01);
            *reinterpret_cast<float2*>(&C[(size_t)r1 * N + col]) = make_float2(v10, v11);
        }
    }
}

// --------------------------- weight transpose --------------------------------
__global__ void wtrans(const float* __restrict__ W, float* __restrict__ WT,
                       int K, int N) {
    int i = blockIdx.x * 256 + threadIdx.x;
    if (i < K * N) {
        int k = i / N, n = i % N;
        WT[(size_t)n * K + k] = W[i];
    }
}

// ------------------------------ reductions ----------------------------------
__device__ __forceinline__ void block_reduce2(float& a, float& b) {
    __shared__ float sa[8], sb[8];
    int lane = threadIdx.x & 31, w = threadIdx.x >> 5;
    #pragma unroll
    for (int o = 16; o; o >>= 1) {
        a += __shfl_xor_sync(0xffffffffu, a, o);
        b += __shfl_xor_sync(0xffffffffu, b, o);
    }
    if (lane == 0) { sa[w] = a; sb[w] = b; }
    __syncthreads();
    if (w == 0) {
        a = (lane < 8) ? sa[lane] : 0.0f;
        b = (lane < 8) ? sb[lane] : 0.0f;
        #pragma unroll
        for (int o = 4; o; o >>= 1) {
            a += __shfl_xor_sync(0xffffffffu, a, o);
            b += __shfl_xor_sync(0xffffffffu, b, o);
        }
        if (lane == 0) { sa[0] = a; sb[0] = b; }
    }
    __syncthreads();
    a = sa[0]; b = sb[0];
}

// --------------------------- embedding + LN ---------------------------------
__global__ void embed_ln(const int* __restrict__ ids, const float* __restrict__ inW,
                         const float* __restrict__ inb, const float* __restrict__ tok,
                         const float* __restrict__ g,  const float* __restrict__ bb,
                         float* __restrict__ X) {
    int tt = blockIdx.x, tid = threadIdx.x;
    float f[NFEAT];
    #pragma unroll
    for (int i = 0; i < NFEAT; i++) f[i] = (float)ids[tt * NFEAT + i];
    int d0 = tid, d1 = tid + 256;
    float v0 = inb[d0] + tok[d0];
    float v1 = inb[d1] + tok[d1];
    #pragma unroll
    for (int i = 0; i < NFEAT; i++) {
        v0 += f[i] * inW[i * DIM + d0];
        v1 += f[i] * inW[i * DIM + d1];
    }
    float s = v0 + v1, q = v0 * v0 + v1 * v1;
    block_reduce2(s, q);
    float mu  = s * (1.0f / DIM);
    float var = q * (1.0f / DIM) - mu * mu;
    float r   = rsqrtf(var + 1e-12f);
    size_t base = (size_t)tt * DIM;
    X[base + d0] = (v0 - mu) * r * g[d0] + bb[d0];
    X[base + d1] = (v1 - mu) * r * g[d1] + bb[d1];
}

__global__ void ln_res(const float* __restrict__ X, const float* __restrict__ Y,
                       const float* __restrict__ g, const float* __restrict__ bb,
                       float* __restrict__ out) {
    int tt = blockIdx.x, tid = threadIdx.x;
    int d0 = tid, d1 = tid + 256;
    size_t base = (size_t)tt * DIM;
    float v0 = X[base + d0] + Y[base + d0];
    float v1 = X[base + d1] + Y[base + d1];
    float s = v0 + v1, q = v0 * v0 + v1 * v1;
    block_reduce2(s, q);
    float mu  = s * (1.0f / DIM);
    float var = q * (1.0f / DIM) - mu * mu;
    float r   = rsqrtf(var + 1e-12f);
    out[base + d0] = (v0 - mu) * r * g[d0] + bb[d0];
    out[base + d1] = (v1 - mu) * r * g[d1] + bb[d1];
}

// ----------------------- attention scores (direct pe) -----------------------
__global__ void attn_scores_simple(const float* __restrict__ Q,
                                   const float* __restrict__ Km,
                                   const float* __restrict__ dist,
                                   float* __restrict__ SC) {
    __shared__ float qs[16][129];
    __shared__ float ks[16][129];
    __shared__ float ds[31][129];
    int tx = threadIdx.x, ty = threadIdx.y;
    int tid = ty * 16 + tx;
    int bh = blockIdx.z;
    int b = bh >> 2, h = bh & 3;
    int l0 = blockIdx.y * 16;
    int r0 = blockIdx.x * 16;
    const float* qb = Q  + (size_t)b * SEQ * DIM + h * DHD;
    const float* kb = Km + (size_t)b * SEQ * DIM + h * DHD;
    #pragma unroll
    for (int j = 0; j < 8; j++) {
        int idx = tid + j * 256;
        int row = idx >> 7, col = idx & 127;
        qs[row][col] = qb[(size_t)(l0 + row) * DIM + col];
        ks[row][col] = kb[(size_t)(r0 + row) * DIM + col];
    }
    int pmin = l0 - r0 + 240;
    for (int idx = tid; idx < 31 * 128; idx += 256) {
        int row = idx >> 7, col = idx & 127;
        ds[row][col] = dist[(size_t)(pmin + row) * DHD + col];
    }
    __syncthreads();
    int prow = ty - tx + 15;
    float s = 0.0f;
    #pragma unroll 8
    for (int d = 0; d < DHD; d++) {
        float qv = qs[ty][d], kv = ks[tx][d], dv = ds[prow][d];
        s += qv * kv + (qv + kv) * dv;
    }
    int l = l0 + ty, r = r0 + tx;
    SC[((size_t)bh * SEQ + l) * SEQ + r] = s;
}

// ------------------------------- softmax -------------------------------------
__global__ void softmax_rows(float* __restrict__ SC, const float* __restrict__ mask) {
    int row  = blockIdx.x * 8 + (threadIdx.x >> 5);
    int lane = threadIdx.x & 31;
    int b = row / (NHEAD * SEQ);
    float* p = SC + (size_t)row * SEQ;
    const float* m = mask + (size_t)b * SEQ;
    float v[8];
    float mx = -1e30f;
    #pragma unroll
    for (int i = 0; i < 8; i++) {
        int r = lane + i * 32;
        float s = p[r] * SM_SCALE + (1.0f - m[r]) * (-1e9f);
        v[i] = s;
        mx = fmaxf(mx, s);
    }
    #pragma unroll
    for (int o = 16; o; o >>= 1) mx = fmaxf(mx, __shfl_xor_sync(0xffffffffu, mx, o));
    float sum = 0.0f;
    #pragma unroll
    for (int i = 0; i < 8; i++) { v[i] = __expf(v[i] - mx); sum += v[i]; }
    #pragma unroll
    for (int o = 16; o; o >>= 1) sum += __shfl_xor_sync(0xffffffffu, sum, o);
    float inv = 1.0f / sum;
    #pragma unroll
    for (int i = 0; i < 8; i++) p[lane + i * 32] = v[i] * inv;
}

// ------------------------------ ctx = P @ V ----------------------------------
__global__ void attn_ctx_simple(const float* __restrict__ P,
                                const float* __restrict__ V,
                                float* __restrict__ CTX) {
    __shared__ float Ps[16][17];
    __shared__ float Vs[16][17];
    int tx = threadIdx.x, ty = threadIdx.y;
    int bh = blockIdx.z;
    int b = bh >> 2, h = bh & 3;
    int l0 = blockIdx.y * 16;
    int n0 = blockIdx.x * 16;
    const float* Pp = P + (size_t)bh * SEQ * SEQ;
    const float* Vb = V + (size_t)b * SEQ * DIM + h * DHD;
    float acc = 0.0f;
    for (int k0 = 0; k0 < SEQ; k0 += 16) {
        Ps[ty][tx] = Pp[(size_t)(l0 + ty) * SEQ + k0 + tx];
        Vs[ty][tx] = Vb[(size_t)(k0 + ty) * DIM + n0 + tx];
        __syncthreads();
        #pragma unroll
        for (int kk = 0; kk < 16; kk++)
            acc += Ps[ty][kk] * Vs[kk][tx];
        __syncthreads();
    }
    CTX[(size_t)b * SEQ * DIM + (size_t)(l0 + ty) * DIM + h * DHD + n0 + tx] = acc;
}

// ------------------------------ host driver ----------------------------------
extern "C" void kernel_launch(void* const* d_in, const int* in_sizes, int n_in,
                              void* d_out, int out_size) {
    (void)in_sizes; (void)n_in; (void)out_size;
    const int*   ids  = (const int*)  d_in[0];
    const float* mask = (const float*)d_in[1];
    const float* inW  = (const float*)d_in[2];
    const float* inb  = (const float*)d_in[3];
    const float* tok  = (const float*)d_in[4];
    const float* elg  = (const float*)d_in[5];
    const float* elb  = (const float*)d_in[6];
    const float* dist = (const float*)d_in[7];
    const float* Wq   = (const float*)d_in[8];
    const float* bq   = (const float*)d_in[9];
    const float* Wk   = (const float*)d_in[10];
    const float* bk   = (const float*)d_in[11];
    const float* Wv   = (const float*)d_in[12];
    const float* bv   = (const float*)d_in[13];
    const float* Wo   = (const float*)d_in[14];
    const float* bo   = (const float*)d_in[15];
    const float* ln1g = (const float*)d_in[16];
    const float* ln1b = (const float*)d_in[17];
    const float* Wi   = (const float*)d_in[18];
    const float* bi   = (const float*)d_in[19];
    const float* Wo2  = (const float*)d_in[20];
    const float* bo2  = (const float*)d_in[21];
    const float* ln2g = (const float*)d_in[22];
    const float* ln2b = (const float*)d_in[23];
    float* out = (float*)d_out;

    float *X, *Q, *Kb, *V, *CTX, *TMP, *Hb, *SC;
    float *WqT, *WkT, *WvT, *WoT, *WiT, *Wo2T;
    cudaGetSymbolAddress((void**)&X,    g_X);
    cudaGetSymbolAddress((void**)&Q,    g_Q);
    cudaGetSymbolAddress((void**)&Kb,   g_K);
    cudaGetSymbolAddress((void**)&V,    g_V);
    cudaGetSymbolAddress((void**)&CTX,  g_CTX);
    cudaGetSymbolAddress((void**)&TMP,  g_TMP);
    cudaGetSymbolAddress((void**)&Hb,   g_Hb);
    cudaGetSymbolAddress((void**)&SC,   g_SC);
    cudaGetSymbolAddress((void**)&WqT,  g_WqT);
    cudaGetSymbolAddress((void**)&WkT,  g_WkT);
    cudaGetSymbolAddress((void**)&WvT,  g_WvT);
    cudaGetSymbolAddress((void**)&WoT,  g_WoT);
    cudaGetSymbolAddress((void**)&WiT,  g_WiT);
    cudaGetSymbolAddress((void**)&Wo2T, g_Wo2T);

    int gDD = (DIM * DIM + 255) / 256, gDI = (DIM * FFI + 255) / 256;
    for (int l = 0; l < LNUM; l++) {
        wtrans<<<gDD, 256>>>(Wq  + (size_t)l * DIM * DIM, WqT  + (size_t)l * DIM * DIM, DIM, DIM);
        wtrans<<<gDD, 256>>>(Wk  + (size_t)l * DIM * DIM, WkT  + (size_t)l * DIM * DIM, DIM, DIM);
        wtrans<<<gDD, 256>>>(Wv  + (size_t)l * DIM * DIM, WvT  + (size_t)l * DIM * DIM, DIM, DIM);
        wtrans<<<gDD, 256>>>(Wo  + (size_t)l * DIM * DIM, WoT  + (size_t)l * DIM * DIM, DIM, DIM);
        wtrans<<<gDI, 256>>>(Wi  + (size_t)l * DIM * FFI, WiT  + (size_t)l * FFI * DIM, DIM, FFI);
        wtrans<<<gDI, 256>>>(Wo2 + (size_t)l * FFI * DIM, Wo2T + (size_t)l * DIM * FFI, FFI, DIM);
    }

    embed_ln<<<TOK, 256>>>(ids, inW, inb, tok, elg, elb, X);

    dim3 blk(16, 16);
    dim3 gG(DIM / 128, TOK / 128);              // 4 x 256
    dim3 gGi(FFI / 128, TOK / 128);             // 1 x 256
    dim3 gS(SEQ / 16, SEQ / 16, BATCH * NHEAD);
    dim3 gC(DHD / 16, SEQ / 16, BATCH * NHEAD);

    for (int l = 0; l < LNUM; l++) {
        const float* wqt  = WqT  + (size_t)l * DIM * DIM;
        const float* wkt  = WkT  + (size_t)l * DIM * DIM;
        const float* wvt  = WvT  + (size_t)l * DIM * DIM;
        const float* wot  = WoT  + (size_t)l * DIM * DIM;
        const float* wit  = WiT  + (size_t)l * FFI * DIM;
        const float* wo2t = Wo2T + (size_t)l * DIM * FFI;

        gemm_tf32<0><<<gG, 256>>>(X, wqt, bq + l * DIM, Q,  DIM, DIM);
        gemm_tf32<0><<<gG, 256>>>(X, wkt, bk + l * DIM, Kb, DIM, DIM);
        gemm_tf32<0><<<gG, 256>>>(X, wvt, bv + l * DIM, V,  DIM, DIM);

        attn_scores_simple<<<gS, blk>>>(Q, Kb, dist, SC);
        softmax_rows<<<ROWSBH / 8, 256>>>(SC, mask);
        attn_ctx_simple<<<gC, blk>>>(SC, V, CTX);

        gemm_tf32<0><<<gG, 256>>>(CTX, wot, bo + l * DIM, TMP, DIM, DIM);
        ln_res<<<TOK, 256>>>(X, TMP, ln1g + l * DIM, ln1b + l * DIM, X);

        gemm_tf32<1><<<gGi, 256>>>(X, wit, bi + l * FFI, Hb, DIM, FFI);
        gemm_tf32<0><<<gG, 256>>>(Hb, wo2t, bo2 + l * DIM, TMP, FFI, DIM);
        ln_res<<<TOK, 256>>>(X, TMP, ln2g + l * DIM, ln2b + l * DIM,
                             (l == LNUM - 1) ? out : X);
    }
}

// round 6
// speedup vs baseline: 5.9128x; 2.4369x over previous
#include <cuda_runtime.h>
#include <math.h>
#include <stdint.h>

// ---------------------------------------------------------------------------
// ExpressionBert forward, tf32 tensor-core everywhere it matters.
// Dense GEMMs + relative-position projections (QD/KD, skew trick) + attention
// scores (Q.K^T + banded gathers) + ctx (P.V) all on mma.sync m16n8k8 tf32.
// Softmax + LayerNorms in fp32 (verified rounds 2/5).
// ---------------------------------------------------------------------------

#define LNUM   4
#define DIM    512
#define NHEAD  4
#define DHD    128
#define FFI    128
#define SEQ    256
#define BATCH  128
#define NFEAT  6
#define TOK    (BATCH*SEQ)          // 32768
#define ROWSBH (BATCH*NHEAD*SEQ)    // 131072
#define PPAD   512                  // dist rows padded 511 -> 512

#define SM_SCALE 0.08838834764831845f  // 1/sqrt(128)

// ------------------------- static device scratch ---------------------------
__device__ float g_X  [TOK*DIM];
__device__ float g_Q  [TOK*DIM];
__device__ float g_K  [TOK*DIM];
__device__ float g_V  [TOK*DIM];
__device__ float g_CTX[TOK*DIM];
__device__ float g_TMP[TOK*DIM];
__device__ float g_Hb [TOK*FFI];
__device__ float g_SC [(size_t)BATCH*NHEAD*SEQ*SEQ];
__device__ float g_QD [(size_t)ROWSBH*PPAD];
__device__ float g_KD [(size_t)ROWSBH*PPAD];
__device__ float g_dP [PPAD*DHD];

__device__ float g_WqT [LNUM*DIM*DIM];
__device__ float g_WkT [LNUM*DIM*DIM];
__device__ float g_WvT [LNUM*DIM*DIM];
__device__ float g_WoT [LNUM*DIM*DIM];
__device__ float g_WiT [LNUM*FFI*DIM];
__device__ float g_Wo2T[LNUM*DIM*FFI];

// ------------------------------ helpers -------------------------------------
__device__ __forceinline__ float gelu_exact(float x) {
    return 0.5f * x * (1.0f + erff(x * 0.70710678118654752440f));
}

__device__ __forceinline__ uint32_t f2tf32(float f) {
    uint32_t u;
    asm("cvt.rna.tf32.f32 %0, %1;" : "=r"(u) : "f"(f));
    return u;
}

__device__ __forceinline__ void mma_tf32(float* d, const uint32_t* a,
                                         const uint32_t* b) {
    asm volatile(
        "mma.sync.aligned.m16n8k8.row.col.f32.tf32.tf32.f32 "
        "{%0,%1,%2,%3}, {%4,%5,%6,%7}, {%8,%9}, {%0,%1,%2,%3};"
        : "+f"(d[0]), "+f"(d[1]), "+f"(d[2]), "+f"(d[3])
        : "r"(a[0]), "r"(a[1]), "r"(a[2]), "r"(a[3]), "r"(b[0]), "r"(b[1]));
}

#define SST 36

// ----------------------- generic tf32 GEMM (verified) ------------------------
template<int GELU>
__global__ __launch_bounds__(256) void gemm_tf32(
    const float* __restrict__ A,    // [M][K] row-major
    const float* __restrict__ BT,   // [N][K] row-major
    const float* __restrict__ bias,
    float* __restrict__ C,
    int K, int N) {
    __shared__ __align__(16) uint32_t sA[128 * SST];
    __shared__ __align__(16) uint32_t sB[128 * SST];

    int tid  = threadIdx.x;
    int wid  = tid >> 5, lane = tid & 31;
    int g    = lane >> 2, t = lane & 3;
    int m0   = blockIdx.y * 128;
    int n0   = blockIdx.x * 128;
    int wm   = wid >> 1, wn = wid & 1;
    int mbase = wm * 32, nbase = wn * 64;

    float acc[2][8][4];
    #pragma unroll
    for (int i = 0; i < 2; i++)
        #pragma unroll
        for (int j = 0; j < 8; j++)
            #pragma unroll
            for (int q = 0; q < 4; q++) acc[i][j][q] = 0.0f;

    int nch = K >> 5;
    for (int c = 0; c < nch; c++) {
        #pragma unroll
        for (int i = 0; i < 4; i++) {
            int idx = tid + i * 256;
            int row = idx >> 3, seg = idx & 7;
            float4 va = *reinterpret_cast<const float4*>(
                &A[(size_t)(m0 + row) * K + c * 32 + seg * 4]);
            uint32_t* pa = &sA[row * SST + seg * 4];
            pa[0] = f2tf32(va.x); pa[1] = f2tf32(va.y);
            pa[2] = f2tf32(va.z); pa[3] = f2tf32(va.w);
            float4 vb = *reinterpret_cast<const float4*>(
                &BT[(size_t)(n0 + row) * K + c * 32 + seg * 4]);
            uint32_t* pb = &sB[row * SST + seg * 4];
            pb[0] = f2tf32(vb.x); pb[1] = f2tf32(vb.y);
            pb[2] = f2tf32(vb.z); pb[3] = f2tf32(vb.w);
        }
        __syncthreads();
        #pragma unroll
        for (int kk = 0; kk < 32; kk += 8) {
            uint32_t af[2][4];
            #pragma unroll
            for (int mt = 0; mt < 2; mt++) {
                int r = mbase + mt * 16 + g;
                af[mt][0] = sA[r * SST + kk + t];
                af[mt][1] = sA[(r + 8) * SST + kk + t];
                af[mt][2] = sA[r * SST + kk + t + 4];
                af[mt][3] = sA[(r + 8) * SST + kk + t + 4];
            }
            uint32_t bf[8][2];
            #pragma unroll
            for (int nt = 0; nt < 8; nt++) {
                int r = nbase + nt * 8 + g;
                bf[nt][0] = sB[r * SST + kk + t];
                bf[nt][1] = sB[r * SST + kk + t + 4];
            }
            #pragma unroll
            for (int mt = 0; mt < 2; mt++)
                #pragma unroll
                for (int nt = 0; nt < 8; nt++)
                    mma_tf32(acc[mt][nt], af[mt], bf[nt]);
        }
        __syncthreads();
    }

    #pragma unroll
    for (int mt = 0; mt < 2; mt++) {
        #pragma unroll
        for (int nt = 0; nt < 8; nt++) {
            int col = n0 + nbase + nt * 8 + 2 * t;
            float b0 = bias ? bias[col]     : 0.0f;
            float b1 = bias ? bias[col + 1] : 0.0f;
            int r0 = m0 + mbase + mt * 16 + g;
            int r1 = r0 + 8;
            float v00 = acc[mt][nt][0] + b0, v01 = acc[mt][nt][1] + b1;
            float v10 = acc[mt][nt][2] + b0, v11 = acc[mt][nt][3] + b1;
            if (GELU) {
                v00 = gelu_exact(v00); v01 = gelu_exact(v01);
                v10 = gelu_exact(v10); v11 = gelu_exact(v11);
            }
            *reinterpret_cast<float2*>(&C[(size_t)r0 * N + col]) = make_float2(v00, v01);
            *reinterpret_cast<float2*>(&C[(size_t)r1 * N + col]) = make_float2(v10, v11);
        }
    }
}

// -------------------- attention scores via MMA + gathers --------------------
// grid (2 rtile, 2 ltile, B*H). S[l,r] = q_l.k_r + QD[l,p] + KD[r,p], p=l-r+255
__global__ __launch_bounds__(256) void attn_scores_mma(
    const float* __restrict__ Q, const float* __restrict__ Km,
    const float* __restrict__ QD, const float* __restrict__ KD,
    float* __restrict__ SC) {
    __shared__ __align__(16) uint32_t sA[128 * SST];
    __shared__ __align__(16) uint32_t sB[128 * SST];

    int tid  = threadIdx.x;
    int wid  = tid >> 5, lane = tid & 31;
    int g    = lane >> 2, t = lane & 3;
    int bh   = blockIdx.z;
    int b    = bh >> 2, h = bh & 3;
    int l0   = blockIdx.y * 128;
    int r0   = blockIdx.x * 128;
    int wm   = wid >> 1, wn = wid & 1;
    int mbase = wm * 32, nbase = wn * 64;

    const float* Qb = Q  + (size_t)b * SEQ * DIM + h * DHD;
    const float* Kb = Km + (size_t)b * SEQ * DIM + h * DHD;

    float acc[2][8][4];
    #pragma unroll
    for (int i = 0; i < 2; i++)
        #pragma unroll
        for (int j = 0; j < 8; j++)
            #pragma unroll
            for (int q = 0; q < 4; q++) acc[i][j][q] = 0.0f;

    for (int c = 0; c < 4; c++) {       // K-inner = 128
        #pragma unroll
        for (int i = 0; i < 4; i++) {
            int idx = tid + i * 256;
            int row = idx >> 3, seg = idx & 7;
            float4 va = *reinterpret_cast<const float4*>(
                &Qb[(size_t)(l0 + row) * DIM + c * 32 + seg * 4]);
            uint32_t* pa = &sA[row * SST + seg * 4];
            pa[0] = f2tf32(va.x); pa[1] = f2tf32(va.y);
            pa[2] = f2tf32(va.z); pa[3] = f2tf32(va.w);
            float4 vb = *reinterpret_cast<const float4*>(
                &Kb[(size_t)(r0 + row) * DIM + c * 32 + seg * 4]);
            uint32_t* pb = &sB[row * SST + seg * 4];
            pb[0] = f2tf32(vb.x); pb[1] = f2tf32(vb.y);
            pb[2] = f2tf32(vb.z); pb[3] = f2tf32(vb.w);
        }
        __syncthreads();
        #pragma unroll
        for (int kk = 0; kk < 32; kk += 8) {
            uint32_t af[2][4];
            #pragma unroll
            for (int mt = 0; mt < 2; mt++) {
                int r = mbase + mt * 16 + g;
                af[mt][0] = sA[r * SST + kk + t];
                af[mt][1] = sA[(r + 8) * SST + kk + t];
                af[mt][2] = sA[r * SST + kk + t + 4];
                af[mt][3] = sA[(r + 8) * SST + kk + t + 4];
            }
            uint32_t bf[8][2];
            #pragma unroll
            for (int nt = 0; nt < 8; nt++) {
                int r = nbase + nt * 8 + g;
                bf[nt][0] = sB[r * SST + kk + t];
                bf[nt][1] = sB[r * SST + kk + t + 4];
            }
            #pragma unroll
            for (int mt = 0; mt < 2; mt++)
                #pragma unroll
                for (int nt = 0; nt < 8; nt++)
                    mma_tf32(acc[mt][nt], af[mt], bf[nt]);
        }
        __syncthreads();
    }

    // epilogue: add QD/KD band gathers, write SC
    #pragma unroll
    for (int mt = 0; mt < 2; mt++) {
        int ll0 = l0 + mbase + mt * 16 + g;
        int ll1 = ll0 + 8;
        size_t qdr0 = ((size_t)(b * SEQ + ll0) * NHEAD + h) * PPAD;
        size_t qdr1 = ((size_t)(b * SEQ + ll1) * NHEAD + h) * PPAD;
        #pragma unroll
        for (int nt = 0; nt < 8; nt++) {
            int rr0 = r0 + nbase + nt * 8 + 2 * t;
            int rr1 = rr0 + 1;
            size_t kdr0 = ((size_t)(b * SEQ + rr0) * NHEAD + h) * PPAD;
            size_t kdr1 = ((size_t)(b * SEQ + rr1) * NHEAD + h) * PPAD;
            int p00 = ll0 - rr0 + 255, p01 = ll0 - rr1 + 255;
            int p10 = ll1 - rr0 + 255, p11 = ll1 - rr1 + 255;
            float v00 = acc[mt][nt][0] + QD[qdr0 + p00] + KD[kdr0 + p00];
            float v01 = acc[mt][nt][1] + QD[qdr0 + p01] + KD[kdr1 + p01];
            float v10 = acc[mt][nt][2] + QD[qdr1 + p10] + KD[kdr0 + p10];
            float v11 = acc[mt][nt][3] + QD[qdr1 + p11] + KD[kdr1 + p11];
            float* dst0 = &SC[((size_t)bh * SEQ + ll0) * SEQ + rr0];
            float* dst1 = &SC[((size_t)bh * SEQ + ll1) * SEQ + rr0];
            *reinterpret_cast<float2*>(dst0) = make_float2(v00, v01);
            *reinterpret_cast<float2*>(dst1) = make_float2(v10, v11);
        }
    }
}

// --------------------------- ctx = P @ V via MMA ----------------------------
// grid (1, 2 ltile, B*H). A = P[128 l x 256 r], B = V chunk staged [k][d].
#define VST 132
__global__ __launch_bounds__(256) void attn_ctx_mma(
    const float* __restrict__ P, const float* __restrict__ V,
    float* __restrict__ CTX) {
    __shared__ __align__(16) uint32_t sA[128 * SST];
    __shared__ __align__(16) uint32_t sV[32 * VST];

    int tid  = threadIdx.x;
    int wid  = tid >> 5, lane = tid & 31;
    int g    = lane >> 2, t = lane & 3;
    int bh   = blockIdx.z;
    int b    = bh >> 2, h = bh & 3;
    int l0   = blockIdx.y * 128;
    int wm   = wid >> 1, wn = wid & 1;
    int mbase = wm * 32, nbase = wn * 64;

    const float* Pb = P + (size_t)bh * SEQ * SEQ;
    const float* Vb = V + (size_t)b * SEQ * DIM + h * DHD;

    float acc[2][8][4];
    #pragma unroll
    for (int i = 0; i < 2; i++)
        #pragma unroll
        for (int j = 0; j < 8; j++)
            #pragma unroll
            for (int q = 0; q < 4; q++) acc[i][j][q] = 0.0f;

    for (int c = 0; c < 8; c++) {       // K-inner = 256
        #pragma unroll
        for (int i = 0; i < 4; i++) {
            int idx = tid + i * 256;
            int row = idx >> 3, seg = idx & 7;          // P: 128 rows x 32 k
            float4 va = *reinterpret_cast<const float4*>(
                &Pb[(size_t)(l0 + row) * SEQ + c * 32 + seg * 4]);
            uint32_t* pa = &sA[row * SST + seg * 4];
            pa[0] = f2tf32(va.x); pa[1] = f2tf32(va.y);
            pa[2] = f2tf32(va.z); pa[3] = f2tf32(va.w);
            int r   = idx >> 5, dseg = idx & 31;        // V: 32 k x 128 d
            float4 vv = *reinterpret_cast<const float4*>(
                &Vb[(size_t)(c * 32 + r) * DIM + dseg * 4]);
            uint32_t* pv = &sV[r * VST + dseg * 4];
            pv[0] = f2tf32(vv.x); pv[1] = f2tf32(vv.y);
            pv[2] = f2tf32(vv.z); pv[3] = f2tf32(vv.w);
        }
        __syncthreads();
        #pragma unroll
        for (int kk = 0; kk < 32; kk += 8) {
            uint32_t af[2][4];
            #pragma unroll
            for (int mt = 0; mt < 2; mt++) {
                int r = mbase + mt * 16 + g;
                af[mt][0] = sA[r * SST + kk + t];
                af[mt][1] = sA[(r + 8) * SST + kk + t];
                af[mt][2] = sA[r * SST + kk + t + 4];
                af[mt][3] = sA[(r + 8) * SST + kk + t + 4];
            }
            uint32_t bf[8][2];
            #pragma unroll
            for (int nt = 0; nt < 8; nt++) {
                int d = nbase + nt * 8 + g;
                bf[nt][0] = sV[(kk + t) * VST + d];
                bf[nt][1] = sV[(kk + t + 4) * VST + d];
            }
            #pragma unroll
            for (int mt = 0; mt < 2; mt++)
                #pragma unroll
                for (int nt = 0; nt < 8; nt++)
                    mma_tf32(acc[mt][nt], af[mt], bf[nt]);
        }
        __syncthreads();
    }

    #pragma unroll
    for (int mt = 0; mt < 2; mt++) {
        #pragma unroll
        for (int nt = 0; nt < 8; nt++) {
            int col = nbase + nt * 8 + 2 * t;
            int rr0 = l0 + mbase + mt * 16 + g;
            int rr1 = rr0 + 8;
            float* dst0 = &CTX[(size_t)(b * SEQ + rr0) * DIM + h * DHD + col];
            float* dst1 = &CTX[(size_t)(b * SEQ + rr1) * DIM + h * DHD + col];
            *reinterpret_cast<float2*>(dst0) = make_float2(acc[mt][nt][0], acc[mt][nt][1]);
            *reinterpret_cast<float2*>(dst1) = make_float2(acc[mt][nt][2], acc[mt][nt][3]);
        }
    }
}

// --------------------------- small prep kernels -----------------------------
__global__ void wtrans(const float* __restrict__ W, float* __restrict__ WT,
                       int K, int N) {
    int i = blockIdx.x * 256 + threadIdx.x;
    if (i < K * N) {
        int k = i / N, n = i % N;
        WT[(size_t)n * K + k] = W[i];
    }
}

__global__ void dist_pad(const float* __restrict__ dist, float* __restrict__ dP) {
    int i = blockIdx.x * 256 + threadIdx.x;
    if (i < PPAD * DHD) {
        int p = i >> 7;
        dP[i] = (p < 511) ? dist[i] : 0.0f;
    }
}

// ------------------------------ reductions ----------------------------------
__device__ __forceinline__ void block_reduce2(float& a, float& b) {
    __shared__ float sa[8], sb[8];
    int lane = threadIdx.x & 31, w = threadIdx.x >> 5;
    #pragma unroll
    for (int o = 16; o; o >>= 1) {
        a += __shfl_xor_sync(0xffffffffu, a, o);
        b += __shfl_xor_sync(0xffffffffu, b, o);
    }
    if (lane == 0) { sa[w] = a; sb[w] = b; }
    __syncthreads();
    if (w == 0) {
        a = (lane < 8) ? sa[lane] : 0.0f;
        b = (lane < 8) ? sb[lane] : 0.0f;
        #pragma unroll
        for (int o = 4; o; o >>= 1) {
            a += __shfl_xor_sync(0xffffffffu, a, o);
            b += __shfl_xor_sync(0xffffffffu, b, o);
        }
        if (lane == 0) { sa[0] = a; sb[0] = b; }
    }
    __syncthreads();
    a = sa[0]; b = sb[0];
}

// --------------------------- embedding + LN ---------------------------------
__global__ void embed_ln(const int* __restrict__ ids, const float* __restrict__ inW,
                         const float* __restrict__ inb, const float* __restrict__ tok,
                         const float* __restrict__ g,  const float* __restrict__ bb,
                         float* __restrict__ X) {
    int tt = blockIdx.x, tid = threadIdx.x;
    float f[NFEAT];
    #pragma unroll
    for (int i = 0; i < NFEAT; i++) f[i] = (float)ids[tt * NFEAT + i];
    int d0 = tid, d1 = tid + 256;
    float v0 = inb[d0] + tok[d0];
    float v1 = inb[d1] + tok[d1];
    #pragma unroll
    for (int i = 0; i < NFEAT; i++) {
        v0 += f[i] * inW[i * DIM + d0];
        v1 += f[i] * inW[i * DIM + d1];
    }
    float s = v0 + v1, q = v0 * v0 + v1 * v1;
    block_reduce2(s, q);
    float mu  = s * (1.0f / DIM);
    float var = q * (1.0f / DIM) - mu * mu;
    float r   = rsqrtf(var + 1e-12f);
    size_t base = (size_t)tt * DIM;
    X[base + d0] = (v0 - mu) * r * g[d0] + bb[d0];
    X[base + d1] = (v1 - mu) * r * g[d1] + bb[d1];
}

__global__ void ln_res(const float* __restrict__ X, const float* __restrict__ Y,
                       const float* __restrict__ g, const float* __restrict__ bb,
                       float* __restrict__ out) {
    int tt = blockIdx.x, tid = threadIdx.x;
    int d0 = tid, d1 = tid + 256;
    size_t base = (size_t)tt * DIM;
    float v0 = X[base + d0] + Y[base + d0];
    float v1 = X[base + d1] + Y[base + d1];
    float s = v0 + v1, q = v0 * v0 + v1 * v1;
    block_reduce2(s, q);
    float mu  = s * (1.0f / DIM);
    float var = q * (1.0f / DIM) - mu * mu;
    float r   = rsqrtf(var + 1e-12f);
    out[base + d0] = (v0 - mu) * r * g[d0] + bb[d0];
    out[base + d1] = (v1 - mu) * r * g[d1] + bb[d1];
}

// ------------------------------- softmax -------------------------------------
__global__ void softmax_rows(float* __restrict__ SC, const float* __restrict__ mask) {
    int row  = blockIdx.x * 8 + (threadIdx.x >> 5);
    int lane = threadIdx.x & 31;
    int b = row / (NHEAD * SEQ);
    float* p = SC + (size_t)row * SEQ;
    const float* m = mask + (size_t)b * SEQ;
    float v[8];
    float mx = -1e30f;
    #pragma unroll
    for (int i = 0; i < 8; i++) {
        int r = lane + i * 32;
        float s = p[r] * SM_SCALE + (1.0f - m[r]) * (-1e9f);
        v[i] = s;
        mx = fmaxf(mx, s);
    }
    #pragma unroll
    for (int o = 16; o; o >>= 1) mx = fmaxf(mx, __shfl_xor_sync(0xffffffffu, mx, o));
    float sum = 0.0f;
    #pragma unroll
    for (int i = 0; i < 8; i++) { v[i] = __expf(v[i] - mx); sum += v[i]; }
    #pragma unroll
    for (int o = 16; o; o >>= 1) sum += __shfl_xor_sync(0xffffffffu, sum, o);
    float inv = 1.0f / sum;
    #pragma unroll
    for (int i = 0; i < 8; i++) p[lane + i * 32] = v[i] * inv;
}

// ------------------------------ host driver ----------------------------------
extern "C" void kernel_launch(void* const* d_in, const int* in_sizes, int n_in,
                              void* d_out, int out_size) {
    (void)in_sizes; (void)n_in; (void)out_size;
    const int*   ids  = (const int*)  d_in[0];
    const float* mask = (const float*)d_in[1];
    const float* inW  = (const float*)d_in[2];
    const float* inb  = (const float*)d_in[3];
    const float* tok  = (const float*)d_in[4];
    const float* elg  = (const float*)d_in[5];
    const float* elb  = (const float*)d_in[6];
    const float* dist = (const float*)d_in[7];
    const float* Wq   = (const float*)d_in[8];
    const float* bq   = (const float*)d_in[9];
    const float* Wk   = (const float*)d_in[10];
    const float* bk   = (const float*)d_in[11];
    const float* Wv   = (const float*)d_in[12];
    const float* bv   = (const float*)d_in[13];
    const float* Wo   = (const float*)d_in[14];
    const float* bo   = (const float*)d_in[15];
    const float* ln1g = (const float*)d_in[16];
    const float* ln1b = (const float*)d_in[17];
    const float* Wi   = (const float*)d_in[18];
    const float* bi   = (const float*)d_in[19];
    const float* Wo2  = (const float*)d_in[20];
    const float* bo2  = (const float*)d_in[21];
    const float* ln2g = (const float*)d_in[22];
    const float* ln2b = (const float*)d_in[23];
    float* out = (float*)d_out;

    float *X, *Q, *Kb, *V, *CTX, *TMP, *Hb, *SC, *QD, *KD, *dP;
    float *WqT, *WkT, *WvT, *WoT, *WiT, *Wo2T;
    cudaGetSymbolAddress((void**)&X,    g_X);
    cudaGetSymbolAddress((void**)&Q,    g_Q);
    cudaGetSymbolAddress((void**)&Kb,   g_K);
    cudaGetSymbolAddress((void**)&V,    g_V);
    cudaGetSymbolAddress((void**)&CTX,  g_CTX);
    cudaGetSymbolAddress((void**)&TMP,  g_TMP);
    cudaGetSymbolAddress((void**)&Hb,   g_Hb);
    cudaGetSymbolAddress((void**)&SC,   g_SC);
    cudaGetSymbolAddress((void**)&QD,   g_QD);
    cudaGetSymbolAddress((void**)&KD,   g_KD);
    cudaGetSymbolAddress((void**)&dP,   g_dP);
    cudaGetSymbolAddress((void**)&WqT,  g_WqT);
    cudaGetSymbolAddress((void**)&WkT,  g_WkT);
    cudaGetSymbolAddress((void**)&WvT,  g_WvT);
    cudaGetSymbolAddress((void**)&WoT,  g_WoT);
    cudaGetSymbolAddress((void**)&WiT,  g_WiT);
    cudaGetSymbolAddress((void**)&Wo2T, g_Wo2T);

    int gDD = (DIM * DIM + 255) / 256, gDI = (DIM * FFI + 255) / 256;
    for (int l = 0; l < LNUM; l++) {
        wtrans<<<gDD, 256>>>(Wq  + (size_t)l * DIM * DIM, WqT  + (size_t)l * DIM * DIM, DIM, DIM);
        wtrans<<<gDD, 256>>>(Wk  + (size_t)l * DIM * DIM, WkT  + (size_t)l * DIM * DIM, DIM, DIM);
        wtrans<<<gDD, 256>>>(Wv  + (size_t)l * DIM * DIM, WvT  + (size_t)l * DIM * DIM, DIM, DIM);
        wtrans<<<gDD, 256>>>(Wo  + (size_t)l * DIM * DIM, WoT  + (size_t)l * DIM * DIM, DIM, DIM);
        wtrans<<<gDI, 256>>>(Wi  + (size_t)l * DIM * FFI, WiT  + (size_t)l * FFI * DIM, DIM, FFI);
        wtrans<<<gDI, 256>>>(Wo2 + (size_t)l * FFI * DIM, Wo2T + (size_t)l * DIM * FFI, FFI, DIM);
    }
    dist_pad<<<(PPAD * DHD + 255) / 256, 256>>>(dist, dP);

    embed_ln<<<TOK, 256>>>(ids, inW, inb, tok, elg, elb, X);

    dim3 gG(DIM / 128, TOK / 128);               // 4 x 256
    dim3 gGi(FFI / 128, TOK / 128);              // 1 x 256
    dim3 gQD(PPAD / 128, ROWSBH / 128);          // 4 x 1024
    dim3 gS(SEQ / 128, SEQ / 128, BATCH * NHEAD);// 2 x 2 x 512
    dim3 gC(1, SEQ / 128, BATCH * NHEAD);        // 1 x 2 x 512

    for (int l = 0; l < LNUM; l++) {
        const float* wqt  = WqT  + (size_t)l * DIM * DIM;
        const float* wkt  = WkT  + (size_t)l * DIM * DIM;
        const float* wvt  = WvT  + (size_t)l * DIM * DIM;
        const float* wot  = WoT  + (size_t)l * DIM * DIM;
        const float* wit  = WiT  + (size_t)l * FFI * DIM;
        const float* wo2t = Wo2T + (size_t)l * DIM * FFI;

        gemm_tf32<0><<<gG, 256>>>(X, wqt, bq + l * DIM, Q,  DIM, DIM);
        gemm_tf32<0><<<gG, 256>>>(X, wkt, bk + l * DIM, Kb, DIM, DIM);
        gemm_tf32<0><<<gG, 256>>>(X, wvt, bv + l * DIM, V,  DIM, DIM);

        // QD/KD: Q,K reinterpreted as [ROWSBH x 128] @ distPad^T -> [ROWSBH x 512]
        gemm_tf32<0><<<gQD, 256>>>(Q,  dP, nullptr, QD, DHD, PPAD);
        gemm_tf32<0><<<gQD, 256>>>(Kb, dP, nullptr, KD, DHD, PPAD);

        attn_scores_mma<<<gS, 256>>>(Q, Kb, QD, KD, SC);
        softmax_rows<<<ROWSBH / 8, 256>>>(SC, mask);
        attn_ctx_mma<<<gC, 256>>>(SC, V, CTX);

        gemm_tf32<0><<<gG, 256>>>(CTX, wot, bo + l * DIM, TMP, DIM, DIM);
        ln_res<<<TOK, 256>>>(X, TMP, ln1g + l * DIM, ln1b + l * DIM, X);

        gemm_tf32<1><<<gGi, 256>>>(X, wit, bi + l * FFI, Hb, DIM, FFI);
        gemm_tf32<0><<<gG, 256>>>(Hb, wo2t, bo2 + l * DIM, TMP, FFI, DIM);
        ln_res<<<TOK, 256>>>(X, TMP, ln2g + l * DIM, ln2b + l * DIM,
                             (l == LNUM - 1) ? out : X);
    }
}

// round 7
// speedup vs baseline: 7.7804x; 1.3159x over previous
#include <cuda_runtime.h>
#include <math.h>
#include <stdint.h>

// ---------------------------------------------------------------------------
// ExpressionBert forward, tf32 tensor cores + cp.async double-buffered
// pipelines. QD/KD band-restricted to N=384 per M-tile (skew windows).
// Softmax + LayerNorms fp32 (verified). Weights/dist pre-rounded rna->tf32;
// activations truncated by the tf32 MMA hardware (CUTLASS sm80 fast path).
// ---------------------------------------------------------------------------

#define LNUM   4
#define DIM    512
#define NHEAD  4
#define DHD    128
#define FFI    128
#define SEQ    256
#define BATCH  128
#define NFEAT  6
#define TOK    (BATCH*SEQ)          // 32768
#define ROWSBH (BATCH*NHEAD*SEQ)    // 131072
#define QCOLS  384                  // banded QD/KD width
#define DPAD   608                  // dist rows padded 511 -> 608 (max window)

#define SM_SCALE 0.08838834764831845f  // 1/sqrt(128)

// ------------------------- static device scratch ---------------------------
__device__ float g_X  [TOK*DIM];
__device__ float g_Q  [TOK*DIM];
__device__ float g_K  [TOK*DIM];
__device__ float g_V  [TOK*DIM];
__device__ float g_CTX[TOK*DIM];
__device__ float g_TMP[TOK*DIM];
__device__ float g_Hb [TOK*FFI];
__device__ float g_SC [(size_t)BATCH*NHEAD*SEQ*SEQ];
__device__ float g_QD [(size_t)ROWSBH*QCOLS];
__device__ float g_KD [(size_t)ROWSBH*QCOLS];
__device__ float g_dP [DPAD*DHD];

__device__ float g_WqT [LNUM*DIM*DIM];
__device__ float g_WkT [LNUM*DIM*DIM];
__device__ float g_WvT [LNUM*DIM*DIM];
__device__ float g_WoT [LNUM*DIM*DIM];
__device__ float g_WiT [LNUM*FFI*DIM];
__device__ float g_Wo2T[LNUM*DIM*FFI];

// ------------------------------ helpers -------------------------------------
__device__ __forceinline__ uint32_t smem_u32(const void* p) {
    uint32_t a;
    asm("{ .reg .u64 t; cvta.to.shared.u64 t, %1; cvt.u32.u64 %0, t; }"
        : "=r"(a) : "l"(p));
    return a;
}

__device__ __forceinline__ float gelu_exact(float x) {
    return 0.5f * x * (1.0f + erff(x * 0.70710678118654752440f));
}

__device__ __forceinline__ float tf32_rna(float f) {
    uint32_t u;
    asm("cvt.rna.tf32.f32 %0, %1;" : "=r"(u) : "f"(f));
    return __uint_as_float(u);
}

__device__ __forceinline__ void mma_tf32(float* d, const uint32_t* a,
                                         const uint32_t* b) {
    asm volatile(
        "mma.sync.aligned.m16n8k8.row.col.f32.tf32.tf32.f32 "
        "{%0,%1,%2,%3}, {%4,%5,%6,%7}, {%8,%9}, {%0,%1,%2,%3};"
        : "+f"(d[0]), "+f"(d[1]), "+f"(d[2]), "+f"(d[3])
        : "r"(a[0]), "r"(a[1]), "r"(a[2]), "r"(a[3]), "r"(b[0]), "r"(b[1]));
}

__device__ __forceinline__ void cp16(uint32_t saddr, const void* gptr) {
    asm volatile("cp.async.cg.shared.global [%0], [%1], 16;"
                 :: "r"(saddr), "l"(gptr) : "memory");
}
#define CP_COMMIT() asm volatile("cp.async.commit_group;" ::: "memory")
#define CP_WAIT1()  asm volatile("cp.async.wait_group 1;" ::: "memory")

#define SST 36
#define STAGEF 9216            // floats per stage (sA 128*36 + sB 128*36)

// fragment compute step shared by all MMA kernels (verified mapping)
#define FRAG_COMPUTE(sA, sB)                                                   \
    _Pragma("unroll")                                                          \
    for (int kk = 0; kk < 32; kk += 8) {                                       \
        uint32_t af[2][4];                                                     \
        _Pragma("unroll")                                                      \
        for (int mt = 0; mt < 2; mt++) {                                       \
            int r = mbase + mt * 16 + g;                                       \
            af[mt][0] = (sA)[r * SST + kk + t];                                \
            af[mt][1] = (sA)[(r + 8) * SST + kk + t];                          \
            af[mt][2] = (sA)[r * SST + kk + t + 4];                            \
            af[mt][3] = (sA)[(r + 8) * SST + kk + t + 4];                      \
        }                                                                      \
        uint32_t bf[8][2];                                                     \
        _Pragma("unroll")                                                      \
        for (int nt = 0; nt < 8; nt++) {                                       \
            int r = nbase + nt * 8 + g;                                        \
            bf[nt][0] = (sB)[r * SST + kk + t];                                \
            bf[nt][1] = (sB)[r * SST + kk + t + 4];                            \
        }                                                                      \
        _Pragma("unroll")                                                      \
        for (int mt = 0; mt < 2; mt++)                                         \
            _Pragma("unroll")                                                  \
            for (int nt = 0; nt < 8; nt++)                                     \
                mma_tf32(acc[mt][nt], af[mt], bf[nt]);                         \
    }

// ---------------- pipelined tf32 GEMM (cp.async double buffer) --------------
// C[M,N] = A[M,K] @ Beff[N,K]^T + bias (+GELU).
// MODE 0: Beff = BT.  MODE 1: Beff = BT + s0*K (QD window).
// MODE 2: Beff = BT + (224-s0)*K (KD window).  s0 = ((m0 & 1023) >> 2).
template<int GELU, int MODE>
__global__ __launch_bounds__(256) void gemm_pipe(
    const float* __restrict__ A, const float* __restrict__ BT,
    const float* __restrict__ bias, float* __restrict__ C, int K, int N) {
    extern __shared__ float dsm[];
    int tid  = threadIdx.x;
    int wid  = tid >> 5, lane = tid & 31;
    int g    = lane >> 2, t = lane & 3;
    int m0   = blockIdx.y * 128;
    int n0   = blockIdx.x * 128;
    int wm   = wid >> 1, wn = wid & 1;
    int mbase = wm * 32, nbase = wn * 64;

    const float* Beff = BT;
    if (MODE == 1) Beff = BT + (size_t)((m0 & 1023) >> 2) * K;
    if (MODE == 2) Beff = BT + (size_t)(224 - ((m0 & 1023) >> 2)) * K;

    float acc[2][8][4];
    #pragma unroll
    for (int i = 0; i < 2; i++)
        #pragma unroll
        for (int j = 0; j < 8; j++)
            #pragma unroll
            for (int q = 0; q < 4; q++) acc[i][j][q] = 0.0f;

    int nch = K >> 5;
    // prologue: stage chunk 0 into buffer 0
    {
        float* sA = dsm;
        float* sB = dsm + 4608;
        #pragma unroll
        for (int i = 0; i < 4; i++) {
            int idx = tid + i * 256, row = idx >> 3, seg = idx & 7;
            cp16(smem_u32(sA + row * SST + seg * 4),
                 &A[(size_t)(m0 + row) * K + seg * 4]);
            cp16(smem_u32(sB + row * SST + seg * 4),
                 &Beff[(size_t)(n0 + row) * K + seg * 4]);
        }
        CP_COMMIT();
    }
    for (int c = 0; c < nch; c++) {
        if (c + 1 < nch) {
            float* sA = dsm + ((c + 1) & 1) * STAGEF;
            float* sB = sA + 4608;
            #pragma unroll
            for (int i = 0; i < 4; i++) {
                int idx = tid + i * 256, row = idx >> 3, seg = idx & 7;
                cp16(smem_u32(sA + row * SST + seg * 4),
                     &A[(size_t)(m0 + row) * K + (c + 1) * 32 + seg * 4]);
                cp16(smem_u32(sB + row * SST + seg * 4),
                     &Beff[(size_t)(n0 + row) * K + (c + 1) * 32 + seg * 4]);
            }
            CP_COMMIT();
        } else {
            CP_COMMIT();   // empty group keeps wait_group accounting uniform
        }
        CP_WAIT1();
        __syncthreads();
        const uint32_t* sA = (const uint32_t*)(dsm + (c & 1) * STAGEF);
        const uint32_t* sB = sA + 4608;
        FRAG_COMPUTE(sA, sB);
        __syncthreads();
    }

    #pragma unroll
    for (int mt = 0; mt < 2; mt++) {
        #pragma unroll
        for (int nt = 0; nt < 8; nt++) {
            int col = n0 + nbase + nt * 8 + 2 * t;
            float b0 = bias ? bias[col]     : 0.0f;
            float b1 = bias ? bias[col + 1] : 0.0f;
            int r0 = m0 + mbase + mt * 16 + g;
            int r1 = r0 + 8;
            float v00 = acc[mt][nt][0] + b0, v01 = acc[mt][nt][1] + b1;
            float v10 = acc[mt][nt][2] + b0, v11 = acc[mt][nt][3] + b1;
            if (GELU) {
                v00 = gelu_exact(v00); v01 = gelu_exact(v01);
                v10 = gelu_exact(v10); v11 = gelu_exact(v11);
            }
            *reinterpret_cast<float2*>(&C[(size_t)r0 * N + col]) = make_float2(v00, v01);
            *reinterpret_cast<float2*>(&C[(size_t)r1 * N + col]) = make_float2(v10, v11);
        }
    }
}

// -------------------- attention scores via MMA + gathers --------------------
__global__ __launch_bounds__(256) void attn_scores_mma(
    const float* __restrict__ Q, const float* __restrict__ Km,
    const float* __restrict__ QD, const float* __restrict__ KD,
    float* __restrict__ SC) {
    extern __shared__ float dsm[];
    int tid  = threadIdx.x;
    int wid  = tid >> 5, lane = tid & 31;
    int g    = lane >> 2, t = lane & 3;
    int bh   = blockIdx.z;
    int b    = bh >> 2, h = bh & 3;
    int l0   = blockIdx.y * 128;
    int r0   = blockIdx.x * 128;
    int wm   = wid >> 1, wn = wid & 1;
    int mbase = wm * 32, nbase = wn * 64;

    const float* Qb = Q  + (size_t)b * SEQ * DIM + h * DHD;
    const float* Kb = Km + (size_t)b * SEQ * DIM + h * DHD;

    float acc[2][8][4];
    #pragma unroll
    for (int i = 0; i < 2; i++)
        #pragma unroll
        for (int j = 0; j < 8; j++)
            #pragma unroll
            for (int q = 0; q < 4; q++) acc[i][j][q] = 0.0f;

    {
        float* sA = dsm;
        float* sB = dsm + 4608;
        #pragma unroll
        for (int i = 0; i < 4; i++) {
            int idx = tid + i * 256, row = idx >> 3, seg = idx & 7;
            cp16(smem_u32(sA + row * SST + seg * 4),
                 &Qb[(size_t)(l0 + row) * DIM + seg * 4]);
            cp16(smem_u32(sB + row * SST + seg * 4),
                 &Kb[(size_t)(r0 + row) * DIM + seg * 4]);
        }
        CP_COMMIT();
    }
    for (int c = 0; c < 4; c++) {       // K-inner = 128
        if (c + 1 < 4) {
            float* sA = dsm + ((c + 1) & 1) * STAGEF;
            float* sB = sA + 4608;
            #pragma unroll
            for (int i = 0; i < 4; i++) {
                int idx = tid + i * 256, row = idx >> 3, seg = idx & 7;
                cp16(smem_u32(sA + row * SST + seg * 4),
                     &Qb[(size_t)(l0 + row) * DIM + (c + 1) * 32 + seg * 4]);
                cp16(smem_u32(sB + row * SST + seg * 4),
                     &Kb[(size_t)(r0 + row) * DIM + (c + 1) * 32 + seg * 4]);
            }
            CP_COMMIT();
        } else {
            CP_COMMIT();
        }
        CP_WAIT1();
        __syncthreads();
        const uint32_t* sA = (const uint32_t*)(dsm + (c & 1) * STAGEF);
        const uint32_t* sB = sA + 4608;
        FRAG_COMPUTE(sA, sB);
        __syncthreads();
    }

    // epilogue: banded QD/KD gathers.  QD[l,p] -> QDc[l, (l&31)+255-r]
    //                                  KD[r,p] -> KDc[r, l-(r&31)+31]
    #pragma unroll
    for (int mt = 0; mt < 2; mt++) {
        int ll0 = l0 + mbase + mt * 16 + g;
        int ll1 = ll0 + 8;
        size_t qdr0 = ((size_t)(b * SEQ + ll0) * NHEAD + h) * QCOLS;
        size_t qdr1 = ((size_t)(b * SEQ + ll1) * NHEAD + h) * QCOLS;
        #pragma unroll
        for (int nt = 0; nt < 8; nt++) {
            int rr0 = r0 + nbase + nt * 8 + 2 * t;
            int rr1 = rr0 + 1;
            size_t kdr0 = ((size_t)(b * SEQ + rr0) * NHEAD + h) * QCOLS;
            size_t kdr1 = ((size_t)(b * SEQ + rr1) * NHEAD + h) * QCOLS;
            int jq00 = (ll0 & 31) + 255 - rr0, jq01 = jq00 - 1;
            int jq10 = (ll1 & 31) + 255 - rr0, jq11 = jq10 - 1;
            int jk00 = ll0 - (rr0 & 31) + 31,  jk01 = ll0 - (rr1 & 31) + 31;
            int jk10 = ll1 - (rr0 & 31) + 31,  jk11 = ll1 - (rr1 & 31) + 31;
            float v00 = acc[mt][nt][0] + QD[qdr0 + jq00] + KD[kdr0 + jk00];
            float v01 = acc[mt][nt][1] + QD[qdr0 + jq01] + KD[kdr1 + jk01];
            float v10 = acc[mt][nt][2] + QD[qdr1 + jq10] + KD[kdr0 + jk10];
            float v11 = acc[mt][nt][3] + QD[qdr1 + jq11] + KD[kdr1 + jk11];
            float* dst0 = &SC[((size_t)bh * SEQ + ll0) * SEQ + rr0];
            float* dst1 = &SC[((size_t)bh * SEQ + ll1) * SEQ + rr0];
            *reinterpret_cast<float2*>(dst0) = make_float2(v00, v01);
            *reinterpret_cast<float2*>(dst1) = make_float2(v10, v11);
        }
    }
}

// --------------------------- ctx = P @ V via MMA ----------------------------
#define VST 132
#define CSTAGEF (4608 + 32*VST)     // P stage + V stage floats
__global__ __launch_bounds__(256) void attn_ctx_mma(
    const float* __restrict__ P, const float* __restrict__ V,
    float* __restrict__ CTX) {
    extern __shared__ float dsm[];
    int tid  = threadIdx.x;
    int wid  = tid >> 5, lane = tid & 31;
    int g    = lane >> 2, t = lane & 3;
    int bh   = blockIdx.z;
    int b    = bh >> 2, h = bh & 3;
    int l0   = blockIdx.y * 128;
    int wm   = wid >> 1, wn = wid & 1;
    int mbase = wm * 32, nbase = wn * 64;

    const float* Pb = P + (size_t)bh * SEQ * SEQ;
    const float* Vb = V + (size_t)b * SEQ * DIM + h * DHD;

    float acc[2][8][4];
    #pragma unroll
    for (int i = 0; i < 2; i++)
        #pragma unroll
        for (int j = 0; j < 8; j++)
            #pragma unroll
            for (int q = 0; q < 4; q++) acc[i][j][q] = 0.0f;

    {
        float* sA = dsm;
        float* sV = dsm + 4608;
        #pragma unroll
        for (int i = 0; i < 4; i++) {
            int idx = tid + i * 256;
            int row = idx >> 3, seg = idx & 7;
            cp16(smem_u32(sA + row * SST + seg * 4),
                 &Pb[(size_t)(l0 + row) * SEQ + seg * 4]);
            int r = idx >> 5, dseg = idx & 31;
            cp16(smem_u32(sV + r * VST + dseg * 4),
                 &Vb[(size_t)r * DIM + dseg * 4]);
        }
        CP_COMMIT();
    }
    for (int c = 0; c < 8; c++) {       // K-inner = 256
        if (c + 1 < 8) {
            float* sA = dsm + ((c + 1) & 1) * CSTAGEF;
            float* sV = sA + 4608;
            #pragma unroll
            for (int i = 0; i < 4; i++) {
                int idx = tid + i * 256;
                int row = idx >> 3, seg = idx & 7;
                cp16(smem_u32(sA + row * SST + seg * 4),
                     &Pb[(size_t)(l0 + row) * SEQ + (c + 1) * 32 + seg * 4]);
                int r = idx >> 5, dseg = idx & 31;
                cp16(smem_u32(sV + r * VST + dseg * 4),
                     &Vb[(size_t)((c + 1) * 32 + r) * DIM + dseg * 4]);
            }
            CP_COMMIT();
        } else {
            CP_COMMIT();
        }
        CP_WAIT1();
        __syncthreads();
        const uint32_t* sA = (const uint32_t*)(dsm + (c & 1) * CSTAGEF);
        const uint32_t* sV = sA + 4608;
        #pragma unroll
        for (int kk = 0; kk < 32; kk += 8) {
            uint32_t af[2][4];
            #pragma unroll
            for (int mt = 0; mt < 2; mt++) {
                int r = mbase + mt * 16 + g;
                af[mt][0] = sA[r * SST + kk + t];
                af[mt][1] = sA[(r + 8) * SST + kk + t];
                af[mt][2] = sA[r * SST + kk + t + 4];
                af[mt][3] = sA[(r + 8) * SST + kk + t + 4];
            }
            uint32_t bf[8][2];
            #pragma unroll
            for (int nt = 0; nt < 8; nt++) {
                int d = nbase + nt * 8 + g;
                bf[nt][0] = sV[(kk + t) * VST + d];
                bf[nt][1] = sV[(kk + t + 4) * VST + d];
            }
            #pragma unroll
            for (int mt = 0; mt < 2; mt++)
                #pragma unroll
                for (int nt = 0; nt < 8; nt++)
                    mma_tf32(acc[mt][nt], af[mt], bf[nt]);
        }
        __syncthreads();
    }

    #pragma unroll
    for (int mt = 0; mt < 2; mt++) {
        #pragma unroll
        for (int nt = 0; nt < 8; nt++) {
            int col = nbase + nt * 8 + 2 * t;
            int rr0 = l0 + mbase + mt * 16 + g;
            int rr1 = rr0 + 8;
            float* dst0 = &CTX[(size_t)(b * SEQ + rr0) * DIM + h * DHD + col];
            float* dst1 = &CTX[(size_t)(b * SEQ + rr1) * DIM + h * DHD + col];
            *reinterpret_cast<float2*>(dst0) = make_float2(acc[mt][nt][0], acc[mt][nt][1]);
            *reinterpret_cast<float2*>(dst1) = make_float2(acc[mt][nt][2], acc[mt][nt][3]);
        }
    }
}

// --------------------------- small prep kernels -----------------------------
__global__ void wtrans(const float* __restrict__ W, float* __restrict__ WT,
                       int K, int N) {
    int i = blockIdx.x * 256 + threadIdx.x;
    if (i < K * N) {
        int k = i / N, n = i % N;
        WT[(size_t)n * K + k] = tf32_rna(W[i]);
    }
}

__global__ void dist_pad(const float* __restrict__ dist, float* __restrict__ dP) {
    int i = blockIdx.x * 256 + threadIdx.x;
    if (i < DPAD * DHD) {
        int p = i >> 7;
        dP[i] = (p < 511) ? tf32_rna(dist[i]) : 0.0f;
    }
}

// ------------------------------ reductions ----------------------------------
__device__ __forceinline__ void block_reduce2(float& a, float& b) {
    __shared__ float sa[8], sb[8];
    int lane = threadIdx.x & 31, w = threadIdx.x >> 5;
    #pragma unroll
    for (int o = 16; o; o >>= 1) {
        a += __shfl_xor_sync(0xffffffffu, a, o);
        b += __shfl_xor_sync(0xffffffffu, b, o);
    }
    if (lane == 0) { sa[w] = a; sb[w] = b; }
    __syncthreads();
    if (w == 0) {
        a = (lane < 8) ? sa[lane] : 0.0f;
        b = (lane < 8) ? sb[lane] : 0.0f;
        #pragma unroll
        for (int o = 4; o; o >>= 1) {
            a += __shfl_xor_sync(0xffffffffu, a, o);
            b += __shfl_xor_sync(0xffffffffu, b, o);
        }
        if (lane == 0) { sa[0] = a; sb[0] = b; }
    }
    __syncthreads();
    a = sa[0]; b = sb[0];
}

// --------------------------- embedding + LN ---------------------------------
__global__ void embed_ln(const int* __restrict__ ids, const float* __restrict__ inW,
                         const float* __restrict__ inb, const float* __restrict__ tok,
                         const float* __restrict__ g,  const float* __restrict__ bb,
                         float* __restrict__ X) {
    int tt = blockIdx.x, tid = threadIdx.x;
    float f[NFEAT];
    #pragma unroll
    for (int i = 0; i < NFEAT; i++) f[i] = (float)ids[tt * NFEAT + i];
    int d0 = tid, d1 = tid + 256;
    float v0 = inb[d0] + tok[d0];
    float v1 = inb[d1] + tok[d1];
    #pragma unroll
    for (int i = 0; i < NFEAT; i++) {
        v0 += f[i] * inW[i * DIM + d0];
        v1 += f[i] * inW[i * DIM + d1];
    }
    float s = v0 + v1, q = v0 * v0 + v1 * v1;
    block_reduce2(s, q);
    float mu  = s * (1.0f / DIM);
    float var = q * (1.0f / DIM) - mu * mu;
    float r   = rsqrtf(var + 1e-12f);
    size_t base = (size_t)tt * DIM;
    X[base + d0] = (v0 - mu) * r * g[d0] + bb[d0];
    X[base + d1] = (v1 - mu) * r * g[d1] + bb[d1];
}

__global__ void ln_res(const float* __restrict__ X, const float* __restrict__ Y,
                       const float* __restrict__ g, const float* __restrict__ bb,
                       float* __restrict__ out) {
    int tt = blockIdx.x, tid = threadIdx.x;
    int d0 = tid, d1 = tid + 256;
    size_t base = (size_t)tt * DIM;
    float v0 = X[base + d0] + Y[base + d0];
    float v1 = X[base + d1] + Y[base + d1];
    float s = v0 + v1, q = v0 * v0 + v1 * v1;
    block_reduce2(s, q);
    float mu  = s * (1.0f / DIM);
    float var = q * (1.0f / DIM) - mu * mu;
    float r   = rsqrtf(var + 1e-12f);
    out[base + d0] = (v0 - mu) * r * g[d0] + bb[d0];
    out[base + d1] = (v1 - mu) * r * g[d1] + bb[d1];
}

// ------------------------------- softmax -------------------------------------
__global__ void softmax_rows(float* __restrict__ SC, const float* __restrict__ mask) {
    int row  = blockIdx.x * 8 + (threadIdx.x >> 5);
    int lane = threadIdx.x & 31;
    int b = row / (NHEAD * SEQ);
    float* p = SC + (size_t)row * SEQ;
    const float* m = mask + (size_t)b * SEQ;
    float v[8];
    float mx = -1e30f;
    #pragma unroll
    for (int i = 0; i < 8; i++) {
        int r = lane + i * 32;
        float s = p[r] * SM_SCALE + (1.0f - m[r]) * (-1e9f);
        v[i] = s;
        mx = fmaxf(mx, s);
    }
    #pragma unroll
    for (int o = 16; o; o >>= 1) mx = fmaxf(mx, __shfl_xor_sync(0xffffffffu, mx, o));
    float sum = 0.0f;
    #pragma unroll
    for (int i = 0; i < 8; i++) { v[i] = __expf(v[i] - mx); sum += v[i]; }
    #pragma unroll
    for (int o = 16; o; o >>= 1) sum += __shfl_xor_sync(0xffffffffu, sum, o);
    float inv = 1.0f / sum;
    #pragma unroll
    for (int i = 0; i < 8; i++) p[lane + i * 32] = v[i] * inv;
}

// ------------------------------ host driver ----------------------------------
extern "C" void kernel_launch(void* const* d_in, const int* in_sizes, int n_in,
                              void* d_out, int out_size) {
    (void)in_sizes; (void)n_in; (void)out_size;
    const int*   ids  = (const int*)  d_in[0];
    const float* mask = (const float*)d_in[1];
    const float* inW  = (const float*)d_in[2];
    const float* inb  = (const float*)d_in[3];
    const float* tok  = (const float*)d_in[4];
    const float* elg  = (const float*)d_in[5];
    const float* elb  = (const float*)d_in[6];
    const float* dist = (const float*)d_in[7];
    const float* Wq   = (const float*)d_in[8];
    const float* bq   = (const float*)d_in[9];
    const float* Wk   = (const float*)d_in[10];
    const float* bk   = (const float*)d_in[11];
    const float* Wv   = (const float*)d_in[12];
    const float* bv   = (const float*)d_in[13];
    const float* Wo   = (const float*)d_in[14];
    const float* bo   = (const float*)d_in[15];
    const float* ln1g = (const float*)d_in[16];
    const float* ln1b = (const float*)d_in[17];
    const float* Wi   = (const float*)d_in[18];
    const float* bi   = (const float*)d_in[19];
    const float* Wo2  = (const float*)d_in[20];
    const float* bo2  = (const float*)d_in[21];
    const float* ln2g = (const float*)d_in[22];
    const float* ln2b = (const float*)d_in[23];
    float* out = (float*)d_out;

    float *X, *Q, *Kb, *V, *CTX, *TMP, *Hb, *SC, *QD, *KD, *dP;
    float *WqT, *WkT, *WvT, *WoT, *WiT, *Wo2T;
    cudaGetSymbolAddress((void**)&X,    g_X);
    cudaGetSymbolAddress((void**)&Q,    g_Q);
    cudaGetSymbolAddress((void**)&Kb,   g_K);
    cudaGetSymbolAddress((void**)&V,    g_V);
    cudaGetSymbolAddress((void**)&CTX,  g_CTX);
    cudaGetSymbolAddress((void**)&TMP,  g_TMP);
    cudaGetSymbolAddress((void**)&Hb,   g_Hb);
    cudaGetSymbolAddress((void**)&SC,   g_SC);
    cudaGetSymbolAddress((void**)&QD,   g_QD);
    cudaGetSymbolAddress((void**)&KD,   g_KD);
    cudaGetSymbolAddress((void**)&dP,   g_dP);
    cudaGetSymbolAddress((void**)&WqT,  g_WqT);
    cudaGetSymbolAddress((void**)&WkT,  g_WkT);
    cudaGetSymbolAddress((void**)&WvT,  g_WvT);
    cudaGetSymbolAddress((void**)&WoT,  g_WoT);
    cudaGetSymbolAddress((void**)&WiT,  g_WiT);
    cudaGetSymbolAddress((void**)&Wo2T, g_Wo2T);

    const int GEMM_SMEM = 2 * STAGEF * 4;          // 73728
    const int CTX_SMEM  = 2 * CSTAGEF * 4;         // 70656
    cudaFuncSetAttribute(gemm_pipe<0,0>, cudaFuncAttributeMaxDynamicSharedMemorySize, GEMM_SMEM);
    cudaFuncSetAttribute(gemm_pipe<1,0>, cudaFuncAttributeMaxDynamicSharedMemorySize, GEMM_SMEM);
    cudaFuncSetAttribute(gemm_pipe<0,1>, cudaFuncAttributeMaxDynamicSharedMemorySize, GEMM_SMEM);
    cudaFuncSetAttribute(gemm_pipe<0,2>, cudaFuncAttributeMaxDynamicSharedMemorySize, GEMM_SMEM);
    cudaFuncSetAttribute(attn_scores_mma, cudaFuncAttributeMaxDynamicSharedMemorySize, GEMM_SMEM);
    cudaFuncSetAttribute(attn_ctx_mma,    cudaFuncAttributeMaxDynamicSharedMemorySize, CTX_SMEM);

    int gDD = (DIM * DIM + 255) / 256, gDI = (DIM * FFI + 255) / 256;
    for (int l = 0; l < LNUM; l++) {
        wtrans<<<gDD, 256>>>(Wq  + (size_t)l * DIM * DIM, WqT  + (size_t)l * DIM * DIM, DIM, DIM);
        wtrans<<<gDD, 256>>>(Wk  + (size_t)l * DIM * DIM, WkT  + (size_t)l * DIM * DIM, DIM, DIM);
        wtrans<<<gDD, 256>>>(Wv  + (size_t)l * DIM * DIM, WvT  + (size_t)l * DIM * DIM, DIM, DIM);
        wtrans<<<gDD, 256>>>(Wo  + (size_t)l * DIM * DIM, WoT  + (size_t)l * DIM * DIM, DIM, DIM);
        wtrans<<<gDI, 256>>>(Wi  + (size_t)l * DIM * FFI, WiT  + (size_t)l * FFI * DIM, DIM, FFI);
        wtrans<<<gDI, 256>>>(Wo2 + (size_t)l * FFI * DIM, Wo2T + (size_t)l * DIM * FFI, FFI, DIM);
    }
    dist_pad<<<(DPAD * DHD + 255) / 256, 256>>>(dist, dP);

    embed_ln<<<TOK, 256>>>(ids, inW, inb, tok, elg, elb, X);

    dim3 gG(DIM / 128, TOK / 128);                 // 4 x 256
    dim3 gGi(FFI / 128, TOK / 128);                // 1 x 256
    dim3 gQD(QCOLS / 128, ROWSBH / 128);           // 3 x 1024
    dim3 gS(SEQ / 128, SEQ / 128, BATCH * NHEAD);  // 2 x 2 x 512
    dim3 gC(1, SEQ / 128, BATCH * NHEAD);          // 1 x 2 x 512

    for (int l = 0; l < LNUM; l++) {
        const float* wqt  = WqT  + (size_t)l * DIM * DIM;
        const float* wkt  = WkT  + (size_t)l * DIM * DIM;
        const float* wvt  = WvT  + (size_t)l * DIM * DIM;
        const float* wot  = WoT  + (size_t)l * DIM * DIM;
        const float* wit  = WiT  + (size_t)l * FFI * DIM;
        const float* wo2t = Wo2T + (size_t)l * DIM * FFI;

        gemm_pipe<0,0><<<gG, 256, GEMM_SMEM>>>(X, wqt, bq + l * DIM, Q,  DIM, DIM);
        gemm_pipe<0,0><<<gG, 256, GEMM_SMEM>>>(X, wkt, bk + l * DIM, Kb, DIM, DIM);
        gemm_pipe<0,0><<<gG, 256, GEMM_SMEM>>>(X, wvt, bv + l * DIM, V,  DIM, DIM);

        // banded QD/KD: per-M-tile shifted windows into padded dist
        gemm_pipe<0,1><<<gQD, 256, GEMM_SMEM>>>(Q,  dP, nullptr, QD, DHD, QCOLS);
        gemm_pipe<0,2><<<gQD, 256, GEMM_SMEM>>>(Kb, dP, nullptr, KD, DHD, QCOLS);

        attn_scores_mma<<<gS, 256, GEMM_SMEM>>>(Q, Kb, QD, KD, SC);
        softmax_rows<<<ROWSBH / 8, 256>>>(SC, mask);
        attn_ctx_mma<<<gC, 256, CTX_SMEM>>>(SC, V, CTX);

        gemm_pipe<0,0><<<gG, 256, GEMM_SMEM>>>(CTX, wot, bo + l * DIM, TMP, DIM, DIM);
        ln_res<<<TOK, 256>>>(X, TMP, ln1g + l * DIM, ln1b + l * DIM, X);

        gemm_pipe<1,0><<<gGi, 256, GEMM_SMEM>>>(X, wit, bi + l * FFI, Hb, DIM, FFI);
        gemm_pipe<0,0><<<gG, 256, GEMM_SMEM>>>(Hb, wo2t, bo2 + l * DIM, TMP, FFI, DIM);
        ln_res<<<TOK, 256>>>(X, TMP, ln2g + l * DIM, ln2b + l * DIM,
                             (l == LNUM - 1) ? out : X);
    }
}

// round 8
// speedup vs baseline: 8.4006x; 1.0797x over previous
#include <cuda_runtime.h>
#include <math.h>
#include <stdint.h>

// ---------------------------------------------------------------------------
// ExpressionBert forward. tf32 mma.sync + cp.async pipelines everywhere.
// Round 8: scores+softmax+ctx fused into one flash-style kernel (S kept in
// registers, P staged through smem); warp-per-token LayerNorms.
// ---------------------------------------------------------------------------

#define LNUM   4
#define DIM    512
#define NHEAD  4
#define DHD    128
#define FFI    128
#define SEQ    256
#define BATCH  128
#define NFEAT  6
#define TOK    (BATCH*SEQ)          // 32768
#define ROWSBH (BATCH*NHEAD*SEQ)    // 131072
#define QCOLS  384
#define DPAD   608

#define SM_SCALE 0.08838834764831845f  // 1/sqrt(128)

// ------------------------- static device scratch ---------------------------
__device__ float g_X  [TOK*DIM];
__device__ float g_Q  [TOK*DIM];
__device__ float g_K  [TOK*DIM];
__device__ float g_V  [TOK*DIM];
__device__ float g_CTX[TOK*DIM];
__device__ float g_TMP[TOK*DIM];
__device__ float g_Hb [TOK*FFI];
__device__ float g_QD [(size_t)ROWSBH*QCOLS];
__device__ float g_KD [(size_t)ROWSBH*QCOLS];
__device__ float g_dP [DPAD*DHD];

__device__ float g_WqT [LNUM*DIM*DIM];
__device__ float g_WkT [LNUM*DIM*DIM];
__device__ float g_WvT [LNUM*DIM*DIM];
__device__ float g_WoT [LNUM*DIM*DIM];
__device__ float g_WiT [LNUM*FFI*DIM];
__device__ float g_Wo2T[LNUM*DIM*FFI];

// ------------------------------ helpers -------------------------------------
__device__ __forceinline__ uint32_t smem_u32(const void* p) {
    uint32_t a;
    asm("{ .reg .u64 t; cvta.to.shared.u64 t, %1; cvt.u32.u64 %0, t; }"
        : "=r"(a) : "l"(p));
    return a;
}

__device__ __forceinline__ float gelu_exact(float x) {
    return 0.5f * x * (1.0f + erff(x * 0.70710678118654752440f));
}

__device__ __forceinline__ float tf32_rna(float f) {
    uint32_t u;
    asm("cvt.rna.tf32.f32 %0, %1;" : "=r"(u) : "f"(f));
    return __uint_as_float(u);
}

__device__ __forceinline__ void mma_tf32(float* d, const uint32_t* a,
                                         const uint32_t* b) {
    asm volatile(
        "mma.sync.aligned.m16n8k8.row.col.f32.tf32.tf32.f32 "
        "{%0,%1,%2,%3}, {%4,%5,%6,%7}, {%8,%9}, {%0,%1,%2,%3};"
        : "+f"(d[0]), "+f"(d[1]), "+f"(d[2]), "+f"(d[3])
        : "r"(a[0]), "r"(a[1]), "r"(a[2]), "r"(a[3]), "r"(b[0]), "r"(b[1]));
}

__device__ __forceinline__ void cp16(uint32_t saddr, const void* gptr) {
    asm volatile("cp.async.cg.shared.global [%0], [%1], 16;"
                 :: "r"(saddr), "l"(gptr) : "memory");
}
#define CP_COMMIT() asm volatile("cp.async.commit_group;" ::: "memory")
#define CP_WAIT1()  asm volatile("cp.async.wait_group 1;" ::: "memory")

#define SST 36
#define STAGEF 9216

#define FRAG_COMPUTE(sA, sB)                                                   \
    _Pragma("unroll")                                                          \
    for (int kk = 0; kk < 32; kk += 8) {                                       \
        uint32_t af[2][4];                                                     \
        _Pragma("unroll")                                                      \
        for (int mt = 0; mt < 2; mt++) {                                       \
            int r = mbase + mt * 16 + g;                                       \
            af[mt][0] = (sA)[r * SST + kk + t];                                \
            af[mt][1] = (sA)[(r + 8) * SST + kk + t];                          \
            af[mt][2] = (sA)[r * SST + kk + t + 4];                            \
            af[mt][3] = (sA)[(r + 8) * SST + kk + t + 4];                      \
        }                                                                      \
        uint32_t bf[8][2];                                                     \
        _Pragma("unroll")                                                      \
        for (int nt = 0; nt < 8; nt++) {                                       \
            int r = nbase + nt * 8 + g;                                        \
            bf[nt][0] = (sB)[r * SST + kk + t];                                \
            bf[nt][1] = (sB)[r * SST + kk + t + 4];                            \
        }                                                                      \
        _Pragma("unroll")                                                      \
        for (int mt = 0; mt < 2; mt++)                                         \
            _Pragma("unroll")                                                  \
            for (int nt = 0; nt < 8; nt++)                                     \
                mma_tf32(acc[mt][nt], af[mt], bf[nt]);                         \
    }

// ---------------- pipelined tf32 GEMM (verified round 7) --------------------
template<int GELU, int MODE>
__global__ __launch_bounds__(256) void gemm_pipe(
    const float* __restrict__ A, const float* __restrict__ BT,
    const float* __restrict__ bias, float* __restrict__ C, int K, int N) {
    extern __shared__ float dsm[];
    int tid  = threadIdx.x;
    int wid  = tid >> 5, lane = tid & 31;
    int g    = lane >> 2, t = lane & 3;
    int m0   = blockIdx.y * 128;
    int n0   = blockIdx.x * 128;
    int wm   = wid >> 1, wn = wid & 1;
    int mbase = wm * 32, nbase = wn * 64;

    const float* Beff = BT;
    if (MODE == 1) Beff = BT + (size_t)((m0 & 1023) >> 2) * K;
    if (MODE == 2) Beff = BT + (size_t)(224 - ((m0 & 1023) >> 2)) * K;

    float acc[2][8][4];
    #pragma unroll
    for (int i = 0; i < 2; i++)
        #pragma unroll
        for (int j = 0; j < 8; j++)
            #pragma unroll
            for (int q = 0; q < 4; q++) acc[i][j][q] = 0.0f;

    int nch = K >> 5;
    {
        float* sA = dsm;
        float* sB = dsm + 4608;
        #pragma unroll
        for (int i = 0; i < 4; i++) {
            int idx = tid + i * 256, row = idx >> 3, seg = idx & 7;
            cp16(smem_u32(sA + row * SST + seg * 4),
                 &A[(size_t)(m0 + row) * K + seg * 4]);
            cp16(smem_u32(sB + row * SST + seg * 4),
                 &Beff[(size_t)(n0 + row) * K + seg * 4]);
        }
        CP_COMMIT();
    }
    for (int c = 0; c < nch; c++) {
        if (c + 1 < nch) {
            float* sA = dsm + ((c + 1) & 1) * STAGEF;
            float* sB = sA + 4608;
            #pragma unroll
            for (int i = 0; i < 4; i++) {
                int idx = tid + i * 256, row = idx >> 3, seg = idx & 7;
                cp16(smem_u32(sA + row * SST + seg * 4),
                     &A[(size_t)(m0 + row) * K + (c + 1) * 32 + seg * 4]);
                cp16(smem_u32(sB + row * SST + seg * 4),
                     &Beff[(size_t)(n0 + row) * K + (c + 1) * 32 + seg * 4]);
            }
            CP_COMMIT();
        } else {
            CP_COMMIT();
        }
        CP_WAIT1();
        __syncthreads();
        const uint32_t* sA = (const uint32_t*)(dsm + (c & 1) * STAGEF);
        const uint32_t* sB = sA + 4608;
        FRAG_COMPUTE(sA, sB);
        __syncthreads();
    }

    #pragma unroll
    for (int mt = 0; mt < 2; mt++) {
        #pragma unroll
        for (int nt = 0; nt < 8; nt++) {
            int col = n0 + nbase + nt * 8 + 2 * t;
            float b0 = bias ? bias[col]     : 0.0f;
            float b1 = bias ? bias[col + 1] : 0.0f;
            int r0 = m0 + mbase + mt * 16 + g;
            int r1 = r0 + 8;
            float v00 = acc[mt][nt][0] + b0, v01 = acc[mt][nt][1] + b1;
            float v10 = acc[mt][nt][2] + b0, v11 = acc[mt][nt][3] + b1;
            if (GELU) {
                v00 = gelu_exact(v00); v01 = gelu_exact(v01);
                v10 = gelu_exact(v10); v11 = gelu_exact(v11);
            }
            *reinterpret_cast<float2*>(&C[(size_t)r0 * N + col]) = make_float2(v00, v01);
            *reinterpret_cast<float2*>(&C[(size_t)r1 * N + col]) = make_float2(v10, v11);
        }
    }
}

// ------------- fused attention: scores + softmax + ctx ----------------------
// grid (SEQ/128, B*H), 256 threads. Phase 1: S[128 l][256 r] in registers
// (warp tile 32 l x 128 r), QD/KD gathers + scale + mask, in-register softmax.
// P -> smem (stride 260), phase 2: ctx = P @ V with cp.async-staged V chunks.
#define PST 260
#define VST 132
// smem float offsets
#define OFF_Q0  0
#define OFF_Q1  4608
#define OFF_K0  9216
#define OFF_K1  18432
#define OFF_P   0            // aliases Q/K staging (dead by then)
#define OFF_V0  33280
#define OFF_V1  37504
#define OFF_RED 41728        // 512 floats: [0,256) max, [256,512) sum
#define FUSED_SMEMF 42240

__global__ __launch_bounds__(256) void fused_attn(
    const float* __restrict__ Q, const float* __restrict__ Km,
    const float* __restrict__ V,
    const float* __restrict__ QD, const float* __restrict__ KD,
    const float* __restrict__ mask, float* __restrict__ CTX) {
    extern __shared__ float dsm[];
    int tid  = threadIdx.x;
    int wid  = tid >> 5, lane = tid & 31;
    int g    = lane >> 2, t = lane & 3;
    int l0   = blockIdx.x * 128;
    int bh   = blockIdx.y;
    int b    = bh >> 2, h = bh & 3;
    int wm   = wid >> 1, wn = wid & 1;
    int mbase = wm * 32;          // l offset of warp
    int nbase2 = wn * 64;         // phase-2 n (d) offset

    const float* Qb = Q  + (size_t)b * SEQ * DIM + h * DHD;
    const float* Kb = Km + (size_t)b * SEQ * DIM + h * DHD;
    const float* Vb = V  + (size_t)b * SEQ * DIM + h * DHD;

    // ---------------- phase 1: S = Q.K^T (warp: 32 l x 128 r) ---------------
    float acc[2][16][4];
    #pragma unroll
    for (int i = 0; i < 2; i++)
        #pragma unroll
        for (int j = 0; j < 16; j++)
            #pragma unroll
            for (int q = 0; q < 4; q++) acc[i][j][q] = 0.0f;

    // stage chunk 0
    {
        float* sQ = dsm + OFF_Q0;
        float* sK = dsm + OFF_K0;
        #pragma unroll
        for (int i = 0; i < 4; i++) {
            int idx = tid + i * 256, row = idx >> 3, seg = idx & 7;
            cp16(smem_u32(sQ + row * SST + seg * 4),
                 &Qb[(size_t)(l0 + row) * DIM + seg * 4]);
        }
        #pragma unroll
        for (int i = 0; i < 8; i++) {
            int idx = tid + i * 256, row = idx >> 3, seg = idx & 7;
            cp16(smem_u32(sK + row * SST + seg * 4),
                 &Kb[(size_t)row * DIM + seg * 4]);
        }
        CP_COMMIT();
    }
    for (int c = 0; c < 4; c++) {           // K-inner = DHD = 128
        if (c + 1 < 4) {
            float* sQ = dsm + ((c + 1) & 1 ? OFF_Q1 : OFF_Q0);
            float* sK = dsm + ((c + 1) & 1 ? OFF_K1 : OFF_K0);
            #pragma unroll
            for (int i = 0; i < 4; i++) {
                int idx = tid + i * 256, row = idx >> 3, seg = idx & 7;
                cp16(smem_u32(sQ + row * SST + seg * 4),
                     &Qb[(size_t)(l0 + row) * DIM + (c + 1) * 32 + seg * 4]);
            }
            #pragma unroll
            for (int i = 0; i < 8; i++) {
                int idx = tid + i * 256, row = idx >> 3, seg = idx & 7;
                cp16(smem_u32(sK + row * SST + seg * 4),
                     &Kb[(size_t)row * DIM + (c + 1) * 32 + seg * 4]);
            }
            CP_COMMIT();
        } else {
            CP_COMMIT();
        }
        CP_WAIT1();
        __syncthreads();
        const uint32_t* sQ = (const uint32_t*)(dsm + ((c & 1) ? OFF_Q1 : OFF_Q0));
        const uint32_t* sK = (const uint32_t*)(dsm + ((c & 1) ? OFF_K1 : OFF_K0));
        #pragma unroll
        for (int kk = 0; kk < 32; kk += 8) {
            uint32_t af[2][4];
            #pragma unroll
            for (int mt = 0; mt < 2; mt++) {
                int r = mbase + mt * 16 + g;
                af[mt][0] = sQ[r * SST + kk + t];
                af[mt][1] = sQ[(r + 8) * SST + kk + t];
                af[mt][2] = sQ[r * SST + kk + t + 4];
                af[mt][3] = sQ[(r + 8) * SST + kk + t + 4];
            }
            #pragma unroll
            for (int nth = 0; nth < 2; nth++) {
                uint32_t bf[8][2];
                #pragma unroll
                for (int j = 0; j < 8; j++) {
                    int r = wn * 128 + nth * 64 + j * 8 + g;
                    bf[j][0] = sK[r * SST + kk + t];
                    bf[j][1] = sK[r * SST + kk + t + 4];
                }
                #pragma unroll
                for (int mt = 0; mt < 2; mt++)
                    #pragma unroll
                    for (int j = 0; j < 8; j++)
                        mma_tf32(acc[mt][nth * 8 + j], af[mt], bf[j]);
            }
        }
        __syncthreads();
    }

    // ------------- epilogue: gathers + scale + mask, in place ---------------
    #pragma unroll
    for (int mt = 0; mt < 2; mt++) {
        int ll0 = l0 + mbase + mt * 16 + g;
        int ll1 = ll0 + 8;
        size_t qdr0 = ((size_t)(b * SEQ + ll0) * NHEAD + h) * QCOLS;
        size_t qdr1 = ((size_t)(b * SEQ + ll1) * NHEAD + h) * QCOLS;
        #pragma unroll
        for (int nt = 0; nt < 16; nt++) {
            int rr0 = wn * 128 + nt * 8 + 2 * t;
            int rr1 = rr0 + 1;
            size_t kdr0 = ((size_t)(b * SEQ + rr0) * NHEAD + h) * QCOLS;
            size_t kdr1 = ((size_t)(b * SEQ + rr1) * NHEAD + h) * QCOLS;
            float bias0 = (1.0f - mask[b * SEQ + rr0]) * (-1e9f);
            float bias1 = (1.0f - mask[b * SEQ + rr1]) * (-1e9f);
            int jq00 = (ll0 & 31) + 255 - rr0, jq01 = jq00 - 1;
            int jq10 = (ll1 & 31) + 255 - rr0, jq11 = jq10 - 1;
            int jk00 = ll0 - (rr0 & 31) + 31,  jk01 = ll0 - (rr1 & 31) + 31;
            int jk10 = ll1 - (rr0 & 31) + 31,  jk11 = ll1 - (rr1 & 31) + 31;
            acc[mt][nt][0] = (acc[mt][nt][0] + QD[qdr0 + jq00] + KD[kdr0 + jk00]) * SM_SCALE + bias0;
            acc[mt][nt][1] = (acc[mt][nt][1] + QD[qdr0 + jq01] + KD[kdr1 + jk01]) * SM_SCALE + bias1;
            acc[mt][nt][2] = (acc[mt][nt][2] + QD[qdr1 + jq10] + KD[kdr0 + jk10]) * SM_SCALE + bias0;
            acc[mt][nt][3] = (acc[mt][nt][3] + QD[qdr1 + jq11] + KD[kdr1 + jk11]) * SM_SCALE + bias1;
        }
    }

    // --------------------------- softmax over r -----------------------------
    float* rmax = dsm + OFF_RED;        // [2][128]
    float* rsum = dsm + OFF_RED + 256;  // [2][128]
    float mx[2][2], sm[2][2];
    #pragma unroll
    for (int mt = 0; mt < 2; mt++)
        #pragma unroll
        for (int hf = 0; hf < 2; hf++) {
            float m = -1e30f;
            #pragma unroll
            for (int nt = 0; nt < 16; nt++) {
                m = fmaxf(m, acc[mt][nt][hf * 2]);
                m = fmaxf(m, acc[mt][nt][hf * 2 + 1]);
            }
            m = fmaxf(m, __shfl_xor_sync(0xffffffffu, m, 1));
            m = fmaxf(m, __shfl_xor_sync(0xffffffffu, m, 2));
            mx[mt][hf] = m;
        }
    if (t == 0) {
        #pragma unroll
        for (int mt = 0; mt < 2; mt++)
            #pragma unroll
            for (int hf = 0; hf < 2; hf++) {
                int lrow = mbase + mt * 16 + hf * 8 + g;
                rmax[wn * 128 + lrow] = mx[mt][hf];
            }
    }
    __syncthreads();
    #pragma unroll
    for (int mt = 0; mt < 2; mt++)
        #pragma unroll
        for (int hf = 0; hf < 2; hf++) {
            int lrow = mbase + mt * 16 + hf * 8 + g;
            float m = fmaxf(rmax[lrow], rmax[128 + lrow]);
            float s = 0.0f;
            #pragma unroll
            for (int nt = 0; nt < 16; nt++) {
                float e0 = __expf(acc[mt][nt][hf * 2]     - m);
                float e1 = __expf(acc[mt][nt][hf * 2 + 1] - m);
                acc[mt][nt][hf * 2]     = e0;
                acc[mt][nt][hf * 2 + 1] = e1;
                s += e0 + e1;
            }
            s += __shfl_xor_sync(0xffffffffu, s, 1);
            s += __shfl_xor_sync(0xffffffffu, s, 2);
            sm[mt][hf] = s;
            if (t == 0) rsum[wn * 128 + lrow] = s;
        }
    __syncthreads();
    #pragma unroll
    for (int mt = 0; mt < 2; mt++)
        #pragma unroll
        for (int hf = 0; hf < 2; hf++) {
            int lrow = mbase + mt * 16 + hf * 8 + g;
            float inv = 1.0f / (rsum[lrow] + rsum[128 + lrow]);
            #pragma unroll
            for (int nt = 0; nt < 16; nt++) {
                acc[mt][nt][hf * 2]     *= inv;
                acc[mt][nt][hf * 2 + 1] *= inv;
            }
            (void)sm[mt][hf];
        }
    __syncthreads();     // Q/K staging reads done; safe to overwrite with P

    // -------------------------- write P to smem ------------------------------
    float* P = dsm + OFF_P;
    #pragma unroll
    for (int mt = 0; mt < 2; mt++) {
        int lr0 = mbase + mt * 16 + g;
        int lr1 = lr0 + 8;
        #pragma unroll
        for (int nt = 0; nt < 16; nt++) {
            int col = wn * 128 + nt * 8 + 2 * t;
            *reinterpret_cast<float2*>(&P[lr0 * PST + col]) =
                make_float2(acc[mt][nt][0], acc[mt][nt][1]);
            *reinterpret_cast<float2*>(&P[lr1 * PST + col]) =
                make_float2(acc[mt][nt][2], acc[mt][nt][3]);
        }
    }
    __syncthreads();

    // ------------------- phase 2: ctx = P @ V (k = 256) ----------------------
    float acc2[2][8][4];
    #pragma unroll
    for (int i = 0; i < 2; i++)
        #pragma unroll
        for (int j = 0; j < 8; j++)
            #pragma unroll
            for (int q = 0; q < 4; q++) acc2[i][j][q] = 0.0f;

    {
        float* sV = dsm + OFF_V0;
        #pragma unroll
        for (int i = 0; i < 4; i++) {
            int idx = tid + i * 256, r = idx >> 5, dseg = idx & 31;
            cp16(smem_u32(sV + r * VST + dseg * 4),
                 &Vb[(size_t)r * DIM + dseg * 4]);
        }
        CP_COMMIT();
    }
    for (int c = 0; c < 8; c++) {
        if (c + 1 < 8) {
            float* sV = dsm + (((c + 1) & 1) ? OFF_V1 : OFF_V0);
            #pragma unroll
            for (int i = 0; i < 4; i++) {
                int idx = tid + i * 256, r = idx >> 5, dseg = idx & 31;
                cp16(smem_u32(sV + r * VST + dseg * 4),
                     &Vb[(size_t)((c + 1) * 32 + r) * DIM + dseg * 4]);
            }
            CP_COMMIT();
        } else {
            CP_COMMIT();
        }
        CP_WAIT1();
        __syncthreads();
        const uint32_t* sP = (const uint32_t*)P;
        const uint32_t* sV = (const uint32_t*)(dsm + ((c & 1) ? OFF_V1 : OFF_V0));
        #pragma unroll
        for (int kk = 0; kk < 32; kk += 8) {
            uint32_t af[2][4];
            #pragma unroll
            for (int mt = 0; mt < 2; mt++) {
                int r = mbase + mt * 16 + g;
                af[mt][0] = sP[r * PST + c * 32 + kk + t];
                af[mt][1] = sP[(r + 8) * PST + c * 32 + kk + t];
                af[mt][2] = sP[r * PST + c * 32 + kk + t + 4];
                af[mt][3] = sP[(r + 8) * PST + c * 32 + kk + t + 4];
            }
            uint32_t bf[8][2];
            #pragma unroll
            for (int nt = 0; nt < 8; nt++) {
                int d = nbase2 + nt * 8 + g;
                bf[nt][0] = sV[(kk + t) * VST + d];
                bf[nt][1] = sV[(kk + t + 4) * VST + d];
            }
            #pragma unroll
            for (int mt = 0; mt < 2; mt++)
                #pragma unroll
                for (int nt = 0; nt < 8; nt++)
                    mma_tf32(acc2[mt][nt], af[mt], bf[nt]);
        }
        __syncthreads();
    }

    #pragma unroll
    for (int mt = 0; mt < 2; mt++) {
        #pragma unroll
        for (int nt = 0; nt < 8; nt++) {
            int col = nbase2 + nt * 8 + 2 * t;
            int rr0 = l0 + mbase + mt * 16 + g;
            int rr1 = rr0 + 8;
            float* dst0 = &CTX[(size_t)(b * SEQ + rr0) * DIM + h * DHD + col];
            float* dst1 = &CTX[(size_t)(b * SEQ + rr1) * DIM + h * DHD + col];
            *reinterpret_cast<float2*>(dst0) = make_float2(acc2[mt][nt][0], acc2[mt][nt][1]);
            *reinterpret_cast<float2*>(dst1) = make_float2(acc2[mt][nt][2], acc2[mt][nt][3]);
        }
    }
}

// --------------------------- small prep kernels -----------------------------
__global__ void wtrans(const float* __restrict__ W, float* __restrict__ WT,
                       int K, int N) {
    int i = blockIdx.x * 256 + threadIdx.x;
    if (i < K * N) {
        int k = i / N, n = i % N;
        WT[(size_t)n * K + k] = tf32_rna(W[i]);
    }
}

__global__ void dist_pad(const float* __restrict__ dist, float* __restrict__ dP) {
    int i = blockIdx.x * 256 + threadIdx.x;
    if (i < DPAD * DHD) {
        int p = i >> 7;
        dP[i] = (p < 511) ? tf32_rna(dist[i]) : 0.0f;
    }
}

// ------------------------------ reductions ----------------------------------
__device__ __forceinline__ void block_reduce2(float& a, float& b) {
    __shared__ float sa[8], sb[8];
    int lane = threadIdx.x & 31, w = threadIdx.x >> 5;
    #pragma unroll
    for (int o = 16; o; o >>= 1) {
        a += __shfl_xor_sync(0xffffffffu, a, o);
        b += __shfl_xor_sync(0xffffffffu, b, o);
    }
    if (lane == 0) { sa[w] = a; sb[w] = b; }
    __syncthreads();
    if (w == 0) {
        a = (lane < 8) ? sa[lane] : 0.0f;
        b = (lane < 8) ? sb[lane] : 0.0f;
        #pragma unroll
        for (int o = 4; o; o >>= 1) {
            a += __shfl_xor_sync(0xffffffffu, a, o);
            b += __shfl_xor_sync(0xffffffffu, b, o);
        }
        if (lane == 0) { sa[0] = a; sb[0] = b; }
    }
    __syncthreads();
    a = sa[0]; b = sb[0];
}

// --------------------------- embedding + LN ---------------------------------
__global__ void embed_ln(const int* __restrict__ ids, const float* __restrict__ inW,
                         const float* __restrict__ inb, const float* __restrict__ tok,
                         const float* __restrict__ g,  const float* __restrict__ bb,
                         float* __restrict__ X) {
    int tt = blockIdx.x, tid = threadIdx.x;
    float f[NFEAT];
    #pragma unroll
    for (int i = 0; i < NFEAT; i++) f[i] = (float)ids[tt * NFEAT + i];
    int d0 = tid, d1 = tid + 256;
    float v0 = inb[d0] + tok[d0];
    float v1 = inb[d1] + tok[d1];
    #pragma unroll
    for (int i = 0; i < NFEAT; i++) {
        v0 += f[i] * inW[i * DIM + d0];
        v1 += f[i] * inW[i * DIM + d1];
    }
    float s = v0 + v1, q = v0 * v0 + v1 * v1;
    block_reduce2(s, q);
    float mu  = s * (1.0f / DIM);
    float var = q * (1.0f / DIM) - mu * mu;
    float r   = rsqrtf(var + 1e-12f);
    size_t base = (size_t)tt * DIM;
    X[base + d0] = (v0 - mu) * r * g[d0] + bb[d0];
    X[base + d1] = (v1 - mu) * r * g[d1] + bb[d1];
}

// warp-per-token residual + LayerNorm: 8 tokens per 256-thread block
__global__ __launch_bounds__(256) void ln_res_w(
    const float* __restrict__ X, const float* __restrict__ Y,
    const float* __restrict__ g, const float* __restrict__ bb,
    float* __restrict__ out) {
    int wid = threadIdx.x >> 5, lane = threadIdx.x & 31;
    int tt = blockIdx.x * 8 + wid;
    size_t base = (size_t)tt * DIM;
    float4 v[4];
    float s = 0.0f, q = 0.0f;
    #pragma unroll
    for (int i = 0; i < 4; i++) {
        int col = i * 128 + lane * 4;
        float4 x4 = *reinterpret_cast<const float4*>(&X[base + col]);
        float4 y4 = *reinterpret_cast<const float4*>(&Y[base + col]);
        v[i].x = x4.x + y4.x; v[i].y = x4.y + y4.y;
        v[i].z = x4.z + y4.z; v[i].w = x4.w + y4.w;
        s += v[i].x + v[i].y + v[i].z + v[i].w;
        q += v[i].x * v[i].x + v[i].y * v[i].y + v[i].z * v[i].z + v[i].w * v[i].w;
    }
    #pragma unroll
    for (int o = 16; o; o >>= 1) {
        s += __shfl_xor_sync(0xffffffffu, s, o);
        q += __shfl_xor_sync(0xffffffffu, q, o);
    }
    float mu  = s * (1.0f / DIM);
    float var = q * (1.0f / DIM) - mu * mu;
    float r   = rsqrtf(var + 1e-12f);
    #pragma unroll
    for (int i = 0; i < 4; i++) {
        int col = i * 128 + lane * 4;
        float4 g4 = *reinterpret_cast<const float4*>(&g[col]);
        float4 b4 = *reinterpret_cast<const float4*>(&bb[col]);
        float4 o4;
        o4.x = (v[i].x - mu) * r * g4.x + b4.x;
        o4.y = (v[i].y - mu) * r * g4.y + b4.y;
        o4.z = (v[i].z - mu) * r * g4.z + b4.z;
        o4.w = (v[i].w - mu) * r * g4.w + b4.w;
        *reinterpret_cast<float4*>(&out[base + col]) = o4;
    }
}

// ------------------------------ host driver ----------------------------------
extern "C" void kernel_launch(void* const* d_in, const int* in_sizes, int n_in,
                              void* d_out, int out_size) {
    (void)in_sizes; (void)n_in; (void)out_size;
    const int*   ids  = (const int*)  d_in[0];
    const float* mask = (const float*)d_in[1];
    const float* inW  = (const float*)d_in[2];
    const float* inb  = (const float*)d_in[3];
    const float* tok  = (const float*)d_in[4];
    const float* elg  = (const float*)d_in[5];
    const float* elb  = (const float*)d_in[6];
    const float* dist = (const float*)d_in[7];
    const float* Wq   = (const float*)d_in[8];
    const float* bq   = (const float*)d_in[9];
    const float* Wk   = (const float*)d_in[10];
    const float* bk   = (const float*)d_in[11];
    const float* Wv   = (const float*)d_in[12];
    const float* bv   = (const float*)d_in[13];
    const float* Wo   = (const float*)d_in[14];
    const float* bo   = (const float*)d_in[15];
    const float* ln1g = (const float*)d_in[16];
    const float* ln1b = (const float*)d_in[17];
    const float* Wi   = (const float*)d_in[18];
    const float* bi   = (const float*)d_in[19];
    const float* Wo2  = (const float*)d_in[20];
    const float* bo2  = (const float*)d_in[21];
    const float* ln2g = (const float*)d_in[22];
    const float* ln2b = (const float*)d_in[23];
    float* out = (float*)d_out;

    float *X, *Q, *Kb, *V, *CTX, *TMP, *Hb, *QD, *KD, *dP;
    float *WqT, *WkT, *WvT, *WoT, *WiT, *Wo2T;
    cudaGetSymbolAddress((void**)&X,    g_X);
    cudaGetSymbolAddress((void**)&Q,    g_Q);
    cudaGetSymbolAddress((void**)&Kb,   g_K);
    cudaGetSymbolAddress((void**)&V,    g_V);
    cudaGetSymbolAddress((void**)&CTX,  g_CTX);
    cudaGetSymbolAddress((void**)&TMP,  g_TMP);
    cudaGetSymbolAddress((void**)&Hb,   g_Hb);
    cudaGetSymbolAddress((void**)&QD,   g_QD);
    cudaGetSymbolAddress((void**)&KD,   g_KD);
    cudaGetSymbolAddress((void**)&dP,   g_dP);
    cudaGetSymbolAddress((void**)&WqT,  g_WqT);
    cudaGetSymbolAddress((void**)&WkT,  g_WkT);
    cudaGetSymbolAddress((void**)&WvT,  g_WvT);
    cudaGetSymbolAddress((void**)&WoT,  g_WoT);
    cudaGetSymbolAddress((void**)&WiT,  g_WiT);
    cudaGetSymbolAddress((void**)&Wo2T, g_Wo2T);

    const int GEMM_SMEM  = 2 * STAGEF * 4;          // 73728
    const int FUSED_SMEM = FUSED_SMEMF * 4;         // 168960
    cudaFuncSetAttribute(gemm_pipe<0,0>, cudaFuncAttributeMaxDynamicSharedMemorySize, GEMM_SMEM);
    cudaFuncSetAttribute(gemm_pipe<1,0>, cudaFuncAttributeMaxDynamicSharedMemorySize, GEMM_SMEM);
    cudaFuncSetAttribute(gemm_pipe<0,1>, cudaFuncAttributeMaxDynamicSharedMemorySize, GEMM_SMEM);
    cudaFuncSetAttribute(gemm_pipe<0,2>, cudaFuncAttributeMaxDynamicSharedMemorySize, GEMM_SMEM);
    cudaFuncSetAttribute(fused_attn,     cudaFuncAttributeMaxDynamicSharedMemorySize, FUSED_SMEM);

    int gDD = (DIM * DIM + 255) / 256, gDI = (DIM * FFI + 255) / 256;
    for (int l = 0; l < LNUM; l++) {
        wtrans<<<gDD, 256>>>(Wq  + (size_t)l * DIM * DIM, WqT  + (size_t)l * DIM * DIM, DIM, DIM);
        wtrans<<<gDD, 256>>>(Wk  + (size_t)l * DIM * DIM, WkT  + (size_t)l * DIM * DIM, DIM, DIM);
        wtrans<<<gDD, 256>>>(Wv  + (size_t)l * DIM * DIM, WvT  + (size_t)l * DIM * DIM, DIM, DIM);
        wtrans<<<gDD, 256>>>(Wo  + (size_t)l * DIM * DIM, WoT  + (size_t)l * DIM * DIM, DIM, DIM);
        wtrans<<<gDI, 256>>>(Wi  + (size_t)l * DIM * FFI, WiT  + (size_t)l * FFI * DIM, DIM, FFI);
        wtrans<<<gDI, 256>>>(Wo2 + (size_t)l * FFI * DIM, Wo2T + (size_t)l * DIM * FFI, FFI, DIM);
    }
    dist_pad<<<(DPAD * DHD + 255) / 256, 256>>>(dist, dP);

    embed_ln<<<TOK, 256>>>(ids, inW, inb, tok, elg, elb, X);

    dim3 gG(DIM / 128, TOK / 128);                 // 4 x 256
    dim3 gGi(FFI / 128, TOK / 128);                // 1 x 256
    dim3 gQD(QCOLS / 128, ROWSBH / 128);           // 3 x 1024
    dim3 gA(SEQ / 128, BATCH * NHEAD);             // 2 x 512

    for (int l = 0; l < LNUM; l++) {
        const float* wqt  = WqT  + (size_t)l * DIM * DIM;
        const float* wkt  = WkT  + (size_t)l * DIM * DIM;
        const float* wvt  = WvT  + (size_t)l * DIM * DIM;
        const float* wot  = WoT  + (size_t)l * DIM * DIM;
        const float* wit  = WiT  + (size_t)l * FFI * DIM;
        const float* wo2t = Wo2T + (size_t)l * DIM * FFI;

        gemm_pipe<0,0><<<gG, 256, GEMM_SMEM>>>(X, wqt, bq + l * DIM, Q,  DIM, DIM);
        gemm_pipe<0,0><<<gG, 256, GEMM_SMEM>>>(X, wkt, bk + l * DIM, Kb, DIM, DIM);
        gemm_pipe<0,0><<<gG, 256, GEMM_SMEM>>>(X, wvt, bv + l * DIM, V,  DIM, DIM);

        gemm_pipe<0,1><<<gQD, 256, GEMM_SMEM>>>(Q,  dP, nullptr, QD, DHD, QCOLS);
        gemm_pipe<0,2><<<gQD, 256, GEMM_SMEM>>>(Kb, dP, nullptr, KD, DHD, QCOLS);

        fused_attn<<<gA, 256, FUSED_SMEM>>>(Q, Kb, V, QD, KD, mask, CTX);

        gemm_pipe<0,0><<<gG, 256, GEMM_SMEM>>>(CTX, wot, bo + l * DIM, TMP, DIM, DIM);
        ln_res_w<<<TOK / 8, 256>>>(X, TMP, ln1g + l * DIM, ln1b + l * DIM, X);

        gemm_pipe<1,0><<<gGi, 256, GEMM_SMEM>>>(X, wit, bi + l * FFI, Hb, DIM, FFI);
        gemm_pipe<0,0><<<gG, 256, GEMM_SMEM>>>(Hb, wo2t, bo2 + l * DIM, TMP, FFI, DIM);
        ln_res_w<<<TOK / 8, 256>>>(X, TMP, ln2g + l * DIM, ln2b + l * DIM,
                                   (l == LNUM - 1) ? out : X);
    }
}